// round 1
// baseline (speedup 1.0000x reference)
#include <cuda_runtime.h>
#include <cstdint>

#define Bb 16
#define Nn 4096
#define KS 64
#define Dd 1024
#define Hh 8
#define DHh 128

// ---------------- scratch (device globals; no allocation allowed) ----------------
__device__ float g_vn[(size_t)Bb * Nn * Dd];      // 256 MB
__device__ float g_Wqk[Dd * Dd];
__device__ float g_Wvo[Dd * Dd];
__device__ float g_slots[Bb * KS * Dd];
__device__ float g_sn[Bb * KS * Dd];
__device__ float g_q[Bb * KS * Dd];
__device__ float g_attn[(size_t)Bb * KS * Nn];    // 16.7 MB
__device__ float g_u1[Bb * KS * Dd];
__device__ float g_qkv[Bb * KS * 3 * Dd];
__device__ float g_P[Bb * Hh * KS * KS];
__device__ float g_sa[Bb * KS * Dd];
__device__ float g_tmp[Bb * KS * Dd];
__device__ float g_h[Bb * KS * Dd];
__device__ float g_t[Bb * KS * 2 * Dd];

// ---------------- helpers ----------------
__device__ __forceinline__ unsigned long long ffma2(unsigned long long a,
                                                    unsigned long long b,
                                                    unsigned long long c) {
    unsigned long long d;
    asm("fma.rn.f32x2 %0, %1, %2, %3;" : "=l"(d) : "l"(a), "l"(b), "l"(c));
    return d;
}
__device__ __forceinline__ unsigned long long pack2f(float x) {
    unsigned long long d;
    asm("mov.b64 %0, {%1, %1};" : "=l"(d) : "f"(x));
    return d;
}
__device__ __forceinline__ float gelu_exact(float x) {
    return 0.5f * x * (1.0f + erff(x * 0.7071067811865476f));
}

// ---------------- LayerNorm (row length D=1024), optional residual, in-place safe ----------------
__global__ void __launch_bounds__(256) ln_kernel(const float* __restrict__ x,
                                                 const float* __restrict__ res,
                                                 const float* __restrict__ gam,
                                                 const float* __restrict__ bet,
                                                 float* __restrict__ y) {
    int row = blockIdx.x;
    int tid = threadIdx.x;
    float4 v = ((const float4*)(x + (size_t)row * Dd))[tid];
    if (res) {
        float4 r = ((const float4*)(res + (size_t)row * Dd))[tid];
        v.x += r.x; v.y += r.y; v.z += r.z; v.w += r.w;
    }
    float s  = v.x + v.y + v.z + v.w;
    float ss = v.x * v.x + v.y * v.y + v.z * v.z + v.w * v.w;
#pragma unroll
    for (int o = 16; o > 0; o >>= 1) {
        s  += __shfl_down_sync(0xffffffffu, s, o);
        ss += __shfl_down_sync(0xffffffffu, ss, o);
    }
    __shared__ float wsum[8], wsq[8];
    __shared__ float smean, srstd;
    int w = tid >> 5, l = tid & 31;
    if (l == 0) { wsum[w] = s; wsq[w] = ss; }
    __syncthreads();
    if (tid == 0) {
        float S = 0.f, SS = 0.f;
#pragma unroll
        for (int i = 0; i < 8; i++) { S += wsum[i]; SS += wsq[i]; }
        float mean = S * (1.0f / Dd);
        float var  = SS * (1.0f / Dd) - mean * mean;
        smean = mean;
        srstd = rsqrtf(var + 1e-5f);
    }
    __syncthreads();
    float mean = smean, rstd = srstd;
    float4 gg = ((const float4*)gam)[tid];
    float4 bb = ((const float4*)bet)[tid];
    float4 o;
    o.x = (v.x - mean) * rstd * gg.x + bb.x;
    o.y = (v.y - mean) * rstd * gg.y + bb.y;
    o.z = (v.z - mean) * rstd * gg.z + bb.z;
    o.w = (v.w - mean) * rstd * gg.w + bb.w;
    ((float4*)(y + (size_t)row * Dd))[tid] = o;
}

// ---------------- broadcast slot_init -> slots ----------------
__global__ void __launch_bounds__(256) bcast_slots(const float* __restrict__ si,
                                                   float* __restrict__ slots) {
    int idx = blockIdx.x * 256 + threadIdx.x;   // B*K*D = 1M total
    slots[idx] = si[idx & (KS * Dd - 1)];
}

// ---------------- softmax over SLOT axis (K=64) of attn[B][K][N] ----------------
__global__ void __launch_bounds__(256) softmax_slots(float* __restrict__ attn) {
    int idx = blockIdx.x * 256 + threadIdx.x;   // over B*N
    int b = idx >> 12;
    int n = idx & (Nn - 1);
    float* p = attn + (size_t)b * KS * Nn + n;
    float m = -1e30f;
#pragma unroll 8
    for (int k = 0; k < KS; k++) m = fmaxf(m, p[(size_t)k * Nn]);
    float s = 0.f;
#pragma unroll 8
    for (int k = 0; k < KS; k++) s += expf(p[(size_t)k * Nn] - m);
    float inv = 1.0f / s;
#pragma unroll 8
    for (int k = 0; k < KS; k++) p[(size_t)k * Nn] = expf(p[(size_t)k * Nn] - m) * inv;
}

// ---------------- MHA inner: scores + softmax -> P[bh][64][64] ----------------
__global__ void __launch_bounds__(256) mha_scores(const float* __restrict__ qkv,
                                                  float* __restrict__ P) {
    int bh = blockIdx.x;
    int b = bh / Hh, h = bh % Hh;
    const float* base = qkv + (size_t)b * KS * 3 * Dd;
    __shared__ float sk[KS][DHh + 1];
    int tid = threadIdx.x;
    for (int i = tid; i < KS * DHh; i += 256) {
        int kj = i >> 7, dd = i & 127;
        sk[kj][dd] = base[(size_t)kj * 3 * Dd + Dd + h * DHh + dd];
    }
    __syncthreads();
    int w = tid >> 5, lane = tid & 31;
    const float rsDH = 0.08838834764831845f;    // 1/sqrt(128)
    for (int r = 0; r < 8; r++) {
        int qi = w * 8 + r;
        const float* qrow = base + (size_t)qi * 3 * Dd + h * DHh;
        float s0 = 0.f, s1 = 0.f;
#pragma unroll 4
        for (int dd = 0; dd < DHh; dd++) {
            float qd = qrow[dd];
            s0 = fmaf(qd, sk[lane][dd], s0);
            s1 = fmaf(qd, sk[lane + 32][dd], s1);
        }
        s0 *= rsDH; s1 *= rsDH;
        float mx = fmaxf(s0, s1);
#pragma unroll
        for (int o = 16; o > 0; o >>= 1) mx = fmaxf(mx, __shfl_xor_sync(0xffffffffu, mx, o));
        float e0 = expf(s0 - mx), e1 = expf(s1 - mx);
        float sum = e0 + e1;
#pragma unroll
        for (int o = 16; o > 0; o >>= 1) sum += __shfl_xor_sync(0xffffffffu, sum, o);
        float inv = 1.0f / sum;
        P[(size_t)bh * 4096 + qi * 64 + lane]      = e0 * inv;
        P[(size_t)bh * 4096 + qi * 64 + lane + 32] = e1 * inv;
    }
}

// ---------------- MHA inner: sa = P @ V, written into [B,K,D] head-concat layout ----------------
__global__ void __launch_bounds__(256) mha_av(const float* __restrict__ qkv,
                                              const float* __restrict__ P,
                                              float* __restrict__ sa) {
    int bh = blockIdx.x;
    int b = bh / Hh, h = bh % Hh;
    const float* vbase = qkv + (size_t)b * KS * 3 * Dd + 2 * Dd + h * DHh;
    __shared__ float sv[KS][DHh];   // 32 KB
    __shared__ float sp[KS][KS];    // 16 KB
    int tid = threadIdx.x;
    for (int i = tid; i < KS * DHh; i += 256) {
        int kj = i >> 7, dd = i & 127;
        sv[kj][dd] = vbase[(size_t)kj * 3 * Dd + dd];
    }
    for (int i = tid; i < KS * KS; i += 256)
        sp[i >> 6][i & 63] = P[(size_t)bh * 4096 + i];
    __syncthreads();
    int d = tid & 127;
    int half = tid >> 7;
    for (int j0 = 0; j0 < 32; j0 += 4) {
        int qi = half * 32 + j0;
        float a0 = 0.f, a1 = 0.f, a2 = 0.f, a3 = 0.f;
#pragma unroll 8
        for (int kj = 0; kj < KS; kj++) {
            float vv = sv[kj][d];
            a0 = fmaf(sp[qi][kj],     vv, a0);
            a1 = fmaf(sp[qi + 1][kj], vv, a1);
            a2 = fmaf(sp[qi + 2][kj], vv, a2);
            a3 = fmaf(sp[qi + 3][kj], vv, a3);
        }
        float* o = sa + (size_t)b * KS * Dd + (size_t)qi * Dd + h * DHh + d;
        o[0] = a0; o[Dd] = a1; o[2 * Dd] = a2; o[3 * Dd] = a3;
    }
}

// ---------------- generic tiled fp32 GEMM with f32x2 FMA ----------------
// C[m,n] = alpha * sum_k A[m,k] * (TB ? B[n,k] : B[k,n])  (+bias[n]) (gelu?) (+add[m,n])
// All M multiples of 64, N multiples of 128, K multiples of 16 (guaranteed by caller).
#define GBM 64
#define GBN 128
#define GBK 16

template <bool TB>
__global__ void __launch_bounds__(256) gemm_kernel(
    const float* __restrict__ A, const float* __restrict__ Bm, float* __restrict__ C,
    int Kd, int lda, int ldb, int ldc,
    long long sA, long long sB, long long sC,
    float alpha,
    const float* __restrict__ bias,
    const float* __restrict__ add, long long sAdd, int ldadd,
    int act) {
    __shared__ float as[GBK][GBM + 4];
    __shared__ float bs[GBK][GBN + 4];

    int bz = blockIdx.z;
    A += (size_t)bz * sA;
    Bm += (size_t)bz * sB;
    C += (size_t)bz * sC;
    if (add) add += (size_t)bz * sAdd;

    int bm = blockIdx.y * GBM;
    int bn = blockIdx.x * GBN;
    int tid = threadIdx.x;
    int tr = tid >> 4;   // 0..15 (row group)
    int tc = tid & 15;   // 0..15 (col group)

    unsigned long long acc[4][4];
#pragma unroll
    for (int i = 0; i < 4; i++)
#pragma unroll
        for (int j = 0; j < 4; j++) acc[i][j] = 0ULL;

    int am = tid >> 2;       // 0..63
    int akq = tid & 3;       // 0..3

    for (int k0 = 0; k0 < Kd; k0 += GBK) {
        // A tile: 64x16, one float4 per thread along k, store transposed
        {
            float4 va = *(const float4*)(A + (size_t)(bm + am) * lda + k0 + akq * 4);
            as[akq * 4 + 0][am] = va.x;
            as[akq * 4 + 1][am] = va.y;
            as[akq * 4 + 2][am] = va.z;
            as[akq * 4 + 3][am] = va.w;
        }
        // B tile: 16x128
        if (TB) {
#pragma unroll
            for (int r = 0; r < 2; r++) {
                int idx = tid + r * 256;      // 0..511
                int n = idx >> 2;             // 0..127
                int kq = idx & 3;             // 0..3
                float4 vv = *(const float4*)(Bm + (size_t)(bn + n) * ldb + k0 + kq * 4);
                bs[kq * 4 + 0][n] = vv.x;
                bs[kq * 4 + 1][n] = vv.y;
                bs[kq * 4 + 2][n] = vv.z;
                bs[kq * 4 + 3][n] = vv.w;
            }
        } else {
#pragma unroll
            for (int r = 0; r < 2; r++) {
                int idx = tid + r * 256;
                int k = idx >> 5;             // 0..15
                int nq = idx & 31;            // 0..31
                *(float4*)&bs[k][nq * 4] =
                    *(const float4*)(Bm + (size_t)(k0 + k) * ldb + bn + nq * 4);
            }
        }
        __syncthreads();
#pragma unroll
        for (int kk = 0; kk < GBK; kk++) {
            float4 av = *(const float4*)&as[kk][tr * 4];
            ulonglong2 bl = *(const ulonglong2*)&bs[kk][tc * 8];
            ulonglong2 bh = *(const ulonglong2*)&bs[kk][tc * 8 + 4];
            unsigned long long ap;
            ap = pack2f(av.x);
            acc[0][0] = ffma2(ap, bl.x, acc[0][0]);
            acc[0][1] = ffma2(ap, bl.y, acc[0][1]);
            acc[0][2] = ffma2(ap, bh.x, acc[0][2]);
            acc[0][3] = ffma2(ap, bh.y, acc[0][3]);
            ap = pack2f(av.y);
            acc[1][0] = ffma2(ap, bl.x, acc[1][0]);
            acc[1][1] = ffma2(ap, bl.y, acc[1][1]);
            acc[1][2] = ffma2(ap, bh.x, acc[1][2]);
            acc[1][3] = ffma2(ap, bh.y, acc[1][3]);
            ap = pack2f(av.z);
            acc[2][0] = ffma2(ap, bl.x, acc[2][0]);
            acc[2][1] = ffma2(ap, bl.y, acc[2][1]);
            acc[2][2] = ffma2(ap, bh.x, acc[2][2]);
            acc[2][3] = ffma2(ap, bh.y, acc[2][3]);
            ap = pack2f(av.w);
            acc[3][0] = ffma2(ap, bl.x, acc[3][0]);
            acc[3][1] = ffma2(ap, bl.y, acc[3][1]);
            acc[3][2] = ffma2(ap, bh.x, acc[3][2]);
            acc[3][3] = ffma2(ap, bh.y, acc[3][3]);
        }
        __syncthreads();
    }

    // epilogue
#pragma unroll
    for (int i = 0; i < 4; i++) {
        int m = bm + tr * 4 + i;
        float* crow = C + (size_t)m * ldc + bn + tc * 8;
        const float* arow = add ? (add + (size_t)m * ldadd + bn + tc * 8) : nullptr;
#pragma unroll
        for (int p = 0; p < 4; p++) {
            float lo = __uint_as_float((unsigned)(acc[i][p])) * alpha;
            float hi = __uint_as_float((unsigned)(acc[i][p] >> 32)) * alpha;
            if (bias) {
                int c = bn + tc * 8 + p * 2;
                lo += bias[c];
                hi += bias[c + 1];
            }
            if (act == 1) { lo = gelu_exact(lo); hi = gelu_exact(hi); }
            if (arow) { lo += arow[p * 2]; hi += arow[p * 2 + 1]; }
            crow[p * 2]     = lo;
            crow[p * 2 + 1] = hi;
        }
    }
}

// ---------------- launcher ----------------
extern "C" void kernel_launch(void* const* d_in, const int* in_sizes, int n_in,
                              void* d_out, int out_size) {
    const float* vis       = (const float*)d_in[0];
    const float* slot_init = (const float*)d_in[1];
    const float* ln_vis_g  = (const float*)d_in[2];
    const float* ln_vis_b  = (const float*)d_in[3];
    const float* ln_sl_g   = (const float*)d_in[4];
    const float* ln_sl_b   = (const float*)d_in[5];
    const float* Wq        = (const float*)d_in[6];
    const float* Wk        = (const float*)d_in[7];
    const float* Wv        = (const float*)d_in[8];
    const float* Wo        = (const float*)d_in[9];
    const float* mha_in_w  = (const float*)d_in[10];
    const float* mha_in_b  = (const float*)d_in[11];
    const float* mha_out_w = (const float*)d_in[12];
    const float* mha_out_b = (const float*)d_in[13];
    const float* ln_sa_g   = (const float*)d_in[14];
    const float* ln_sa_b   = (const float*)d_in[15];
    const float* ln_ffn_g  = (const float*)d_in[16];
    const float* ln_ffn_b  = (const float*)d_in[17];
    const float* W1        = (const float*)d_in[18];
    const float* b1        = (const float*)d_in[19];
    const float* W2        = (const float*)d_in[20];
    const float* b2        = (const float*)d_in[21];

    float *vn, *Wqk, *Wvo, *slots, *sn, *q, *attn, *u1, *qkv, *P, *sa, *tmp, *hbuf, *tbuf;
    cudaGetSymbolAddress((void**)&vn,    g_vn);
    cudaGetSymbolAddress((void**)&Wqk,   g_Wqk);
    cudaGetSymbolAddress((void**)&Wvo,   g_Wvo);
    cudaGetSymbolAddress((void**)&slots, g_slots);
    cudaGetSymbolAddress((void**)&sn,    g_sn);
    cudaGetSymbolAddress((void**)&q,     g_q);
    cudaGetSymbolAddress((void**)&attn,  g_attn);
    cudaGetSymbolAddress((void**)&u1,    g_u1);
    cudaGetSymbolAddress((void**)&qkv,   g_qkv);
    cudaGetSymbolAddress((void**)&P,     g_P);
    cudaGetSymbolAddress((void**)&sa,    g_sa);
    cudaGetSymbolAddress((void**)&tmp,   g_tmp);
    cudaGetSymbolAddress((void**)&hbuf,  g_h);
    cudaGetSymbolAddress((void**)&tbuf,  g_t);

    float* out = (float*)d_out;

    // vn = LN(visual_tokens)
    ln_kernel<<<Bb * Nn, 256>>>(vis, nullptr, ln_vis_g, ln_vis_b, vn);

    // Wqk = Wq @ Wk^T (NT), Wvo = Wv @ Wo (NN)
    gemm_kernel<true><<<dim3(Dd / GBN, Dd / GBM, 1), 256>>>(
        Wq, Wk, Wqk, Dd, Dd, Dd, Dd, 0, 0, 0, 1.0f, nullptr, nullptr, 0, 0, 0);
    gemm_kernel<false><<<dim3(Dd / GBN, Dd / GBM, 1), 256>>>(
        Wv, Wo, Wvo, Dd, Dd, Dd, Dd, 0, 0, 0, 1.0f, nullptr, nullptr, 0, 0, 0);

    // slots = broadcast(slot_init)
    bcast_slots<<<(Bb * KS * Dd) / 256, 256>>>(slot_init, slots);

    const int Mfull = Bb * KS;  // 1024
    for (int it = 0; it < 2; it++) {
        // sn = LN(slots)
        ln_kernel<<<Mfull, 256>>>(slots, nullptr, ln_sl_g, ln_sl_b, sn);
        // q = sn @ Wqk   (NN, flat over batch)
        gemm_kernel<false><<<dim3(Dd / GBN, Mfull / GBM, 1), 256>>>(
            sn, Wqk, q, Dd, Dd, Dd, Dd, 0, 0, 0, 1.0f, nullptr, nullptr, 0, 0, 0);
        // attn[b] = (1/32) * q[b] @ vn[b]^T   (NT batched, M=64, N=4096, K=1024)
        gemm_kernel<true><<<dim3(Nn / GBN, 1, Bb), 256>>>(
            q, vn, attn, Dd, Dd, Dd, Nn,
            (long long)KS * Dd, (long long)Nn * Dd, (long long)KS * Nn,
            0.03125f, nullptr, nullptr, 0, 0, 0);
        // aw = softmax over slot axis
        softmax_slots<<<(Bb * Nn) / 256, 256>>>(attn);
        // u1[b] = aw[b] @ vn[b]   (NN batched, M=64, N=1024, K=4096)
        gemm_kernel<false><<<dim3(Dd / GBN, 1, Bb), 256>>>(
            attn, vn, u1, Nn, Nn, Dd, Dd,
            (long long)KS * Nn, (long long)Nn * Dd, (long long)KS * Dd,
            1.0f, nullptr, nullptr, 0, 0, 0);
        // slots = slots + u1 @ Wvo
        gemm_kernel<false><<<dim3(Dd / GBN, Mfull / GBM, 1), 256>>>(
            u1, Wvo, slots, Dd, Dd, Dd, Dd, 0, 0, 0, 1.0f, nullptr, slots, 0, Dd, 0);
        // qkv = slots @ mha_in_w^T + mha_in_b   (NT, N=3072)
        gemm_kernel<true><<<dim3(3 * Dd / GBN, Mfull / GBM, 1), 256>>>(
            slots, mha_in_w, qkv, Dd, Dd, Dd, 3 * Dd, 0, 0, 0, 1.0f, mha_in_b,
            nullptr, 0, 0, 0);
        // per-head attention
        mha_scores<<<Bb * Hh, 256>>>(qkv, P);
        mha_av<<<Bb * Hh, 256>>>(qkv, P, sa);
        // tmp = sa @ mha_out_w^T + mha_out_b
        gemm_kernel<true><<<dim3(Dd / GBN, Mfull / GBM, 1), 256>>>(
            sa, mha_out_w, tmp, Dd, Dd, Dd, Dd, 0, 0, 0, 1.0f, mha_out_b,
            nullptr, 0, 0, 0);
        // slots = LN(slots + tmp)
        ln_kernel<<<Mfull, 256>>>(slots, tmp, ln_sa_g, ln_sa_b, slots);
    }

    // h = LN(slots)
    ln_kernel<<<Mfull, 256>>>(slots, nullptr, ln_ffn_g, ln_ffn_b, hbuf);
    // t = gelu(h @ W1 + b1)   (NN, N=2048)
    gemm_kernel<false><<<dim3(2 * Dd / GBN, Mfull / GBM, 1), 256>>>(
        hbuf, W1, tbuf, Dd, Dd, 2 * Dd, 2 * Dd, 0, 0, 0, 1.0f, b1, nullptr, 0, 0, 1);
    // out = slots + t @ W2 + b2   (NN, K=2048)
    gemm_kernel<false><<<dim3(Dd / GBN, Mfull / GBM, 1), 256>>>(
        tbuf, W2, out, 2 * Dd, 2 * Dd, Dd, Dd, 0, 0, 0, 1.0f, b2, slots, 0, Dd, 0);
}

// round 3
// speedup vs baseline: 2.2359x; 2.2359x over previous
#include <cuda_runtime.h>
#include <cuda_bf16.h>
#include <cstdint>

#define Bb 16
#define Nn 4096
#define KS 64
#define Dd 1024
#define Hh 8
#define DHh 128

// ---------------- scratch (device globals; no allocation allowed) ----------------
__device__ float g_vn[(size_t)Bb * Nn * Dd];      // 256 MB
__device__ float g_Wqk[Dd * Dd];
__device__ float g_Wvo[Dd * Dd];
__device__ float g_slots[Bb * KS * Dd];
__device__ float g_sn[Bb * KS * Dd];
__device__ float g_q[Bb * KS * Dd];
__device__ float g_attn[(size_t)Bb * KS * Nn];    // 16.7 MB
__device__ float g_u1[Bb * KS * Dd];
__device__ float g_qkv[Bb * KS * 3 * Dd];
__device__ float g_P[Bb * Hh * KS * KS];
__device__ float g_sa[Bb * KS * Dd];
__device__ float g_tmp[Bb * KS * Dd];
__device__ float g_h[Bb * KS * Dd];
__device__ float g_t[Bb * KS * 2 * Dd];

__device__ __forceinline__ float gelu_exact(float x) {
    return 0.5f * x * (1.0f + erff(x * 0.7071067811865476f));
}

// ---------------- LayerNorm (row length D=1024), optional residual ----------------
__global__ void __launch_bounds__(256) ln_kernel(const float* __restrict__ x,
                                                 const float* __restrict__ res,
                                                 const float* __restrict__ gam,
                                                 const float* __restrict__ bet,
                                                 float* __restrict__ y) {
    int row = blockIdx.x;
    int tid = threadIdx.x;
    float4 v = ((const float4*)(x + (size_t)row * Dd))[tid];
    if (res) {
        float4 r = ((const float4*)(res + (size_t)row * Dd))[tid];
        v.x += r.x; v.y += r.y; v.z += r.z; v.w += r.w;
    }
    float s  = v.x + v.y + v.z + v.w;
    float ss = v.x * v.x + v.y * v.y + v.z * v.z + v.w * v.w;
#pragma unroll
    for (int o = 16; o > 0; o >>= 1) {
        s  += __shfl_down_sync(0xffffffffu, s, o);
        ss += __shfl_down_sync(0xffffffffu, ss, o);
    }
    __shared__ float wsum[8], wsq[8];
    __shared__ float smean, srstd;
    int w = tid >> 5, l = tid & 31;
    if (l == 0) { wsum[w] = s; wsq[w] = ss; }
    __syncthreads();
    if (tid == 0) {
        float S = 0.f, SS = 0.f;
#pragma unroll
        for (int i = 0; i < 8; i++) { S += wsum[i]; SS += wsq[i]; }
        float mean = S * (1.0f / Dd);
        float var  = SS * (1.0f / Dd) - mean * mean;
        smean = mean;
        srstd = rsqrtf(var + 1e-5f);
    }
    __syncthreads();
    float mean = smean, rstd = srstd;
    float4 gg = ((const float4*)gam)[tid];
    float4 bb = ((const float4*)bet)[tid];
    float4 o;
    o.x = (v.x - mean) * rstd * gg.x + bb.x;
    o.y = (v.y - mean) * rstd * gg.y + bb.y;
    o.z = (v.z - mean) * rstd * gg.z + bb.z;
    o.w = (v.w - mean) * rstd * gg.w + bb.w;
    ((float4*)(y + (size_t)row * Dd))[tid] = o;
}

__global__ void __launch_bounds__(256) bcast_slots(const float* __restrict__ si,
                                                   float* __restrict__ slots) {
    int idx = blockIdx.x * 256 + threadIdx.x;
    slots[idx] = si[idx & (KS * Dd - 1)];
}

// ---------------- softmax over SLOT axis (K=64) of attn[B][K][N] ----------------
__global__ void __launch_bounds__(256) softmax_slots(float* __restrict__ attn) {
    int idx = blockIdx.x * 256 + threadIdx.x;
    int b = idx >> 12;
    int n = idx & (Nn - 1);
    float* p = attn + (size_t)b * KS * Nn + n;
    float m = -1e30f;
#pragma unroll 8
    for (int k = 0; k < KS; k++) m = fmaxf(m, p[(size_t)k * Nn]);
    float s = 0.f;
#pragma unroll 8
    for (int k = 0; k < KS; k++) s += expf(p[(size_t)k * Nn] - m);
    float inv = 1.0f / s;
#pragma unroll 8
    for (int k = 0; k < KS; k++) p[(size_t)k * Nn] = expf(p[(size_t)k * Nn] - m) * inv;
}

// ---------------- MHA inner: scores + softmax -> P[bh][64][64] ----------------
__global__ void __launch_bounds__(256) mha_scores(const float* __restrict__ qkv,
                                                  float* __restrict__ P) {
    int bh = blockIdx.x;
    int b = bh / Hh, h = bh % Hh;
    const float* base = qkv + (size_t)b * KS * 3 * Dd;
    __shared__ float sk[KS][DHh + 1];
    int tid = threadIdx.x;
    for (int i = tid; i < KS * DHh; i += 256) {
        int kj = i >> 7, dd = i & 127;
        sk[kj][dd] = base[(size_t)kj * 3 * Dd + Dd + h * DHh + dd];
    }
    __syncthreads();
    int w = tid >> 5, lane = tid & 31;
    const float rsDH = 0.08838834764831845f;
    for (int r = 0; r < 8; r++) {
        int qi = w * 8 + r;
        const float* qrow = base + (size_t)qi * 3 * Dd + h * DHh;
        float s0 = 0.f, s1 = 0.f;
#pragma unroll 4
        for (int dd = 0; dd < DHh; dd++) {
            float qd = qrow[dd];
            s0 = fmaf(qd, sk[lane][dd], s0);
            s1 = fmaf(qd, sk[lane + 32][dd], s1);
        }
        s0 *= rsDH; s1 *= rsDH;
        float mx = fmaxf(s0, s1);
#pragma unroll
        for (int o = 16; o > 0; o >>= 1) mx = fmaxf(mx, __shfl_xor_sync(0xffffffffu, mx, o));
        float e0 = expf(s0 - mx), e1 = expf(s1 - mx);
        float sum = e0 + e1;
#pragma unroll
        for (int o = 16; o > 0; o >>= 1) sum += __shfl_xor_sync(0xffffffffu, sum, o);
        float inv = 1.0f / sum;
        P[(size_t)bh * 4096 + qi * 64 + lane]      = e0 * inv;
        P[(size_t)bh * 4096 + qi * 64 + lane + 32] = e1 * inv;
    }
}

// ---------------- MHA inner: sa = P @ V ----------------
__global__ void __launch_bounds__(256) mha_av(const float* __restrict__ qkv,
                                              const float* __restrict__ P,
                                              float* __restrict__ sa) {
    int bh = blockIdx.x;
    int b = bh / Hh, h = bh % Hh;
    const float* vbase = qkv + (size_t)b * KS * 3 * Dd + 2 * Dd + h * DHh;
    __shared__ float sv[KS][DHh];
    __shared__ float sp[KS][KS];
    int tid = threadIdx.x;
    for (int i = tid; i < KS * DHh; i += 256) {
        int kj = i >> 7, dd = i & 127;
        sv[kj][dd] = vbase[(size_t)kj * 3 * Dd + dd];
    }
    for (int i = tid; i < KS * KS; i += 256)
        sp[i >> 6][i & 63] = P[(size_t)bh * 4096 + i];
    __syncthreads();
    int d = tid & 127;
    int half = tid >> 7;
    for (int j0 = 0; j0 < 32; j0 += 4) {
        int qi = half * 32 + j0;
        float a0 = 0.f, a1 = 0.f, a2 = 0.f, a3 = 0.f;
#pragma unroll 8
        for (int kj = 0; kj < KS; kj++) {
            float vv = sv[kj][d];
            a0 = fmaf(sp[qi][kj],     vv, a0);
            a1 = fmaf(sp[qi + 1][kj], vv, a1);
            a2 = fmaf(sp[qi + 2][kj], vv, a2);
            a3 = fmaf(sp[qi + 3][kj], vv, a3);
        }
        float* o = sa + (size_t)b * KS * Dd + (size_t)qi * Dd + h * DHh + d;
        o[0] = a0; o[Dd] = a1; o[2 * Dd] = a2; o[3 * Dd] = a3;
    }
}

// ================= Tensor-core GEMM: split-bf16 (hi+lo), mma.sync m16n8k16 =================
// C = alpha * A @ op(B) (+bias) (gelu) (+add).  A row-major [M,K].
// TB=true:  B is [N,K] (row-major over N, K contiguous)  -> "NT"
// TB=false: B is [K,N] (row-major over K, N contiguous)  -> "NN"
// BM in {64,128}, BN=128, BK=32. 256 threads = 8 warps (2 x 4).

#define SSTR 40   // smem row stride in bf16 (32 + 8 pad) -> 20 words, frag-conflict-free

__device__ __forceinline__ void mma_bf16(float* d, const uint32_t* a, uint32_t b0, uint32_t b1) {
    asm volatile(
        "mma.sync.aligned.m16n8k16.row.col.f32.bf16.bf16.f32 "
        "{%0,%1,%2,%3}, {%4,%5,%6,%7}, {%8,%9}, {%0,%1,%2,%3};\n"
        : "+f"(d[0]), "+f"(d[1]), "+f"(d[2]), "+f"(d[3])
        : "r"(a[0]), "r"(a[1]), "r"(a[2]), "r"(a[3]), "r"(b0), "r"(b1));
}

__device__ __forceinline__ void split4(float4 v, __nv_bfloat16* hp, __nv_bfloat16* lp) {
    __nv_bfloat16 h0 = __float2bfloat16(v.x);
    __nv_bfloat16 h1 = __float2bfloat16(v.y);
    __nv_bfloat16 h2 = __float2bfloat16(v.z);
    __nv_bfloat16 h3 = __float2bfloat16(v.w);
    __nv_bfloat162* hp2 = (__nv_bfloat162*)hp;
    hp2[0] = __nv_bfloat162(h0, h1);
    hp2[1] = __nv_bfloat162(h2, h3);
    __nv_bfloat16 l0 = __float2bfloat16(v.x - __bfloat162float(h0));
    __nv_bfloat16 l1 = __float2bfloat16(v.y - __bfloat162float(h1));
    __nv_bfloat16 l2 = __float2bfloat16(v.z - __bfloat162float(h2));
    __nv_bfloat16 l3 = __float2bfloat16(v.w - __bfloat162float(h3));
    __nv_bfloat162* lp2 = (__nv_bfloat162*)lp;
    lp2[0] = __nv_bfloat162(l0, l1);
    lp2[1] = __nv_bfloat162(l2, l3);
}

template <int BM, bool TB>
__global__ void __launch_bounds__(256) gemm_mma(
    const float* __restrict__ A, const float* __restrict__ Bm, float* __restrict__ C,
    int Kd, int lda, int ldb, int ldc,
    long long sA, long long sB, long long sC,
    float alpha,
    const float* __restrict__ bias,
    const float* __restrict__ add, long long sAdd, int ldadd,
    int act) {
    constexpr int MS = BM / 32;     // m-subtiles per warp
    constexpr int PA = BM / 32;     // A-load passes

    __shared__ __align__(16) __nv_bfloat16 sAh[BM * SSTR];
    __shared__ __align__(16) __nv_bfloat16 sAl[BM * SSTR];
    __shared__ __align__(16) __nv_bfloat16 sBh[128 * SSTR];
    __shared__ __align__(16) __nv_bfloat16 sBl[128 * SSTR];

    int bz = blockIdx.z;
    A += (size_t)bz * sA;
    Bm += (size_t)bz * sB;
    C += (size_t)bz * sC;
    if (add) add += (size_t)bz * sAdd;

    int bm = blockIdx.y * BM;
    int bn = blockIdx.x * 128;
    int tid = threadIdx.x, lane = tid & 31, wid = tid >> 5;
    int wm = (wid >> 2) * (BM / 2);
    int wn = (wid & 3) * 32;
    int r = lane >> 2, cc = lane & 3;

    float acc[MS][4][4];
#pragma unroll
    for (int m = 0; m < MS; m++)
#pragma unroll
        for (int n = 0; n < 4; n++)
#pragma unroll
            for (int i = 0; i < 4; i++) acc[m][n][i] = 0.f;

    float4 pa[PA];
    float4 pb4[4];
    float pbs[16];

    int T = Kd / 32;
    // initial gmem loads
    {
#pragma unroll
        for (int p = 0; p < PA; p++) {
            int f = tid + p * 256, row = f >> 3, kq = f & 7;
            pa[p] = *(const float4*)(A + (size_t)(bm + row) * lda + kq * 4);
        }
        if (TB) {
#pragma unroll
            for (int p = 0; p < 4; p++) {
                int f = tid + p * 256, row = f >> 3, kq = f & 7;
                pb4[p] = *(const float4*)(Bm + (size_t)(bn + row) * ldb + kq * 4);
            }
        } else {
#pragma unroll
            for (int p = 0; p < 16; p++) {
                int f = tid + p * 256, kk = f >> 7, n = f & 127;
                pbs[p] = Bm[(size_t)kk * ldb + bn + n];
            }
        }
    }

    for (int t = 0; t < T; t++) {
        __syncthreads();
        // regs -> smem (with hi/lo split)
#pragma unroll
        for (int p = 0; p < PA; p++) {
            int f = tid + p * 256, row = f >> 3, kq = f & 7;
            split4(pa[p], &sAh[row * SSTR + kq * 4], &sAl[row * SSTR + kq * 4]);
        }
        if (TB) {
#pragma unroll
            for (int p = 0; p < 4; p++) {
                int f = tid + p * 256, row = f >> 3, kq = f & 7;
                split4(pb4[p], &sBh[row * SSTR + kq * 4], &sBl[row * SSTR + kq * 4]);
            }
        } else {
#pragma unroll
            for (int p = 0; p < 16; p++) {
                int f = tid + p * 256, kk = f >> 7, n = f & 127;
                float x = pbs[p];
                __nv_bfloat16 h = __float2bfloat16(x);
                sBh[n * SSTR + kk] = h;
                sBl[n * SSTR + kk] = __float2bfloat16(x - __bfloat162float(h));
            }
        }
        __syncthreads();
        // prefetch next tile
        if (t + 1 < T) {
            int k0 = (t + 1) * 32;
#pragma unroll
            for (int p = 0; p < PA; p++) {
                int f = tid + p * 256, row = f >> 3, kq = f & 7;
                pa[p] = *(const float4*)(A + (size_t)(bm + row) * lda + k0 + kq * 4);
            }
            if (TB) {
#pragma unroll
                for (int p = 0; p < 4; p++) {
                    int f = tid + p * 256, row = f >> 3, kq = f & 7;
                    pb4[p] = *(const float4*)(Bm + (size_t)(bn + row) * ldb + k0 + kq * 4);
                }
            } else {
#pragma unroll
                for (int p = 0; p < 16; p++) {
                    int f = tid + p * 256, kk = f >> 7, n = f & 127;
                    pbs[p] = Bm[(size_t)(k0 + kk) * ldb + bn + n];
                }
            }
        }
        // compute: 2 k16 steps on current tile
        const uint32_t* AhW = (const uint32_t*)sAh;
        const uint32_t* AlW = (const uint32_t*)sAl;
        const uint32_t* BhW = (const uint32_t*)sBh;
        const uint32_t* BlW = (const uint32_t*)sBl;
#pragma unroll
        for (int s = 0; s < 2; s++) {
            int kb = s * 8;
            uint32_t ah[MS][4], al[MS][4];
#pragma unroll
            for (int ms = 0; ms < MS; ms++) {
                int row0 = wm + ms * 16;
                int b0 = (row0 + r) * 20 + kb + cc;
                int b8 = (row0 + r + 8) * 20 + kb + cc;
                ah[ms][0] = AhW[b0]; ah[ms][1] = AhW[b8];
                ah[ms][2] = AhW[b0 + 4]; ah[ms][3] = AhW[b8 + 4];
                al[ms][0] = AlW[b0]; al[ms][1] = AlW[b8];
                al[ms][2] = AlW[b0 + 4]; al[ms][3] = AlW[b8 + 4];
            }
#pragma unroll
            for (int ns = 0; ns < 4; ns++) {
                int nb = (wn + ns * 8 + r) * 20 + kb + cc;
                uint32_t bh0 = BhW[nb], bh1 = BhW[nb + 4];
                uint32_t bl0 = BlW[nb], bl1 = BlW[nb + 4];
#pragma unroll
                for (int ms = 0; ms < MS; ms++) {
                    mma_bf16(acc[ms][ns], ah[ms], bh0, bh1);
                    mma_bf16(acc[ms][ns], ah[ms], bl0, bl1);
                    mma_bf16(acc[ms][ns], al[ms], bh0, bh1);
                }
            }
        }
    }

    // epilogue
#pragma unroll
    for (int ms = 0; ms < MS; ms++) {
        int i0 = bm + wm + ms * 16 + r;
#pragma unroll
        for (int ns = 0; ns < 4; ns++) {
            int j = bn + wn + ns * 8 + 2 * cc;
            float v00 = acc[ms][ns][0] * alpha, v01 = acc[ms][ns][1] * alpha;
            float v10 = acc[ms][ns][2] * alpha, v11 = acc[ms][ns][3] * alpha;
            if (bias) {
                float bj0 = bias[j], bj1 = bias[j + 1];
                v00 += bj0; v01 += bj1; v10 += bj0; v11 += bj1;
            }
            if (act == 1) {
                v00 = gelu_exact(v00); v01 = gelu_exact(v01);
                v10 = gelu_exact(v10); v11 = gelu_exact(v11);
            }
            if (add) {
                v00 += add[(size_t)i0 * ldadd + j];
                v01 += add[(size_t)i0 * ldadd + j + 1];
                v10 += add[(size_t)(i0 + 8) * ldadd + j];
                v11 += add[(size_t)(i0 + 8) * ldadd + j + 1];
            }
            float2 lo2; lo2.x = v00; lo2.y = v01;
            float2 hi2; hi2.x = v10; hi2.y = v11;
            *(float2*)(C + (size_t)i0 * ldc + j) = lo2;
            *(float2*)(C + (size_t)(i0 + 8) * ldc + j) = hi2;
        }
    }
}

// ---------------- launcher ----------------
extern "C" void kernel_launch(void* const* d_in, const int* in_sizes, int n_in,
                              void* d_out, int out_size) {
    const float* vis       = (const float*)d_in[0];
    const float* slot_init = (const float*)d_in[1];
    const float* ln_vis_g  = (const float*)d_in[2];
    const float* ln_vis_b  = (const float*)d_in[3];
    const float* ln_sl_g   = (const float*)d_in[4];
    const float* ln_sl_b   = (const float*)d_in[5];
    const float* Wq        = (const float*)d_in[6];
    const float* Wk        = (const float*)d_in[7];
    const float* Wv        = (const float*)d_in[8];
    const float* Wo        = (const float*)d_in[9];
    const float* mha_in_w  = (const float*)d_in[10];
    const float* mha_in_b  = (const float*)d_in[11];
    const float* mha_out_w = (const float*)d_in[12];
    const float* mha_out_b = (const float*)d_in[13];
    const float* ln_sa_g   = (const float*)d_in[14];
    const float* ln_sa_b   = (const float*)d_in[15];
    const float* ln_ffn_g  = (const float*)d_in[16];
    const float* ln_ffn_b  = (const float*)d_in[17];
    const float* W1        = (const float*)d_in[18];
    const float* b1        = (const float*)d_in[19];
    const float* W2        = (const float*)d_in[20];
    const float* b2        = (const float*)d_in[21];

    float *vn, *Wqk, *Wvo, *slots, *sn, *q, *attn, *u1, *qkv, *P, *sa, *tmp, *hbuf, *tbuf;
    cudaGetSymbolAddress((void**)&vn,    g_vn);
    cudaGetSymbolAddress((void**)&Wqk,   g_Wqk);
    cudaGetSymbolAddress((void**)&Wvo,   g_Wvo);
    cudaGetSymbolAddress((void**)&slots, g_slots);
    cudaGetSymbolAddress((void**)&sn,    g_sn);
    cudaGetSymbolAddress((void**)&q,     g_q);
    cudaGetSymbolAddress((void**)&attn,  g_attn);
    cudaGetSymbolAddress((void**)&u1,    g_u1);
    cudaGetSymbolAddress((void**)&qkv,   g_qkv);
    cudaGetSymbolAddress((void**)&P,     g_P);
    cudaGetSymbolAddress((void**)&sa,    g_sa);
    cudaGetSymbolAddress((void**)&tmp,   g_tmp);
    cudaGetSymbolAddress((void**)&hbuf,  g_h);
    cudaGetSymbolAddress((void**)&tbuf,  g_t);

    float* out = (float*)d_out;

    // vn = LN(visual_tokens)
    ln_kernel<<<Bb * Nn, 256>>>(vis, nullptr, ln_vis_g, ln_vis_b, vn);

    // Wqk = Wq @ Wk^T (NT), Wvo = Wv @ Wo (NN)
    gemm_mma<128, true><<<dim3(Dd / 128, Dd / 128, 1), 256>>>(
        Wq, Wk, Wqk, Dd, Dd, Dd, Dd, 0, 0, 0, 1.0f, nullptr, nullptr, 0, 0, 0);
    gemm_mma<128, false><<<dim3(Dd / 128, Dd / 128, 1), 256>>>(
        Wv, Wo, Wvo, Dd, Dd, Dd, Dd, 0, 0, 0, 1.0f, nullptr, nullptr, 0, 0, 0);

    bcast_slots<<<(Bb * KS * Dd) / 256, 256>>>(slot_init, slots);

    const int Mfull = Bb * KS;  // 1024
    for (int it = 0; it < 2; it++) {
        ln_kernel<<<Mfull, 256>>>(slots, nullptr, ln_sl_g, ln_sl_b, sn);
        // q = sn @ Wqk (NN)
        gemm_mma<128, false><<<dim3(Dd / 128, Mfull / 128, 1), 256>>>(
            sn, Wqk, q, Dd, Dd, Dd, Dd, 0, 0, 0, 1.0f, nullptr, nullptr, 0, 0, 0);
        // attn[b] = (1/32) * q[b] @ vn[b]^T   (NT, M=64, N=4096, K=1024)
        gemm_mma<64, true><<<dim3(Nn / 128, 1, Bb), 256>>>(
            q, vn, attn, Dd, Dd, Dd, Nn,
            (long long)KS * Dd, (long long)Nn * Dd, (long long)KS * Nn,
            0.03125f, nullptr, nullptr, 0, 0, 0);
        softmax_slots<<<(Bb * Nn) / 256, 256>>>(attn);
        // u1[b] = aw[b] @ vn[b]   (NN, M=64, N=1024, K=4096)
        gemm_mma<64, false><<<dim3(Dd / 128, 1, Bb), 256>>>(
            attn, vn, u1, Nn, Nn, Dd, Dd,
            (long long)KS * Nn, (long long)Nn * Dd, (long long)KS * Dd,
            1.0f, nullptr, nullptr, 0, 0, 0);
        // slots = slots + u1 @ Wvo (NN)
        gemm_mma<128, false><<<dim3(Dd / 128, Mfull / 128, 1), 256>>>(
            u1, Wvo, slots, Dd, Dd, Dd, Dd, 0, 0, 0, 1.0f, nullptr, slots, 0, Dd, 0);
        // qkv = slots @ mha_in_w^T + mha_in_b (NT, N=3072)
        gemm_mma<128, true><<<dim3(3 * Dd / 128, Mfull / 128, 1), 256>>>(
            slots, mha_in_w, qkv, Dd, Dd, Dd, 3 * Dd, 0, 0, 0, 1.0f, mha_in_b,
            nullptr, 0, 0, 0);
        mha_scores<<<Bb * Hh, 256>>>(qkv, P);
        mha_av<<<Bb * Hh, 256>>>(qkv, P, sa);
        // tmp = sa @ mha_out_w^T + mha_out_b (NT)
        gemm_mma<128, true><<<dim3(Dd / 128, Mfull / 128, 1), 256>>>(
            sa, mha_out_w, tmp, Dd, Dd, Dd, Dd, 0, 0, 0, 1.0f, mha_out_b,
            nullptr, 0, 0, 0);
        ln_kernel<<<Mfull, 256>>>(slots, tmp, ln_sa_g, ln_sa_b, slots);
    }

    ln_kernel<<<Mfull, 256>>>(slots, nullptr, ln_ffn_g, ln_ffn_b, hbuf);
    // t = gelu(h @ W1 + b1) (NN, N=2048)
    gemm_mma<128, false><<<dim3(2 * Dd / 128, Mfull / 128, 1), 256>>>(
        hbuf, W1, tbuf, Dd, Dd, 2 * Dd, 2 * Dd, 0, 0, 0, 1.0f, b1, nullptr, 0, 0, 1);
    // out = slots + t @ W2 + b2 (NN, K=2048)
    gemm_mma<128, false><<<dim3(Dd / 128, Mfull / 128, 1), 256>>>(
        tbuf, W2, out, 2 * Dd, 2 * Dd, Dd, Dd, 0, 0, 0, 1.0f, b2, slots, 0, Dd, 0);
}

// round 4
// speedup vs baseline: 2.7771x; 1.2420x over previous
#include <cuda_runtime.h>
#include <cuda_bf16.h>
#include <cstdint>

#define Bb 16
#define Nn 4096
#define KS 64
#define Dd 1024
#define Hh 8
#define DHh 128

typedef __nv_bfloat16 bf16;
typedef __nv_bfloat162 bf162;

// ---------------- scratch (device globals; no allocation allowed) ----------------
// split-bf16 pairs (hi, lo): value = hi + lo, accurate to ~2^-16
__device__ __align__(256) bf16 g_vnh[(size_t)Bb * Nn * Dd];
__device__ __align__(256) bf16 g_vnl[(size_t)Bb * Nn * Dd];
__device__ __align__(256) bf16 g_vnTh[(size_t)Bb * Dd * Nn];
__device__ __align__(256) bf16 g_vnTl[(size_t)Bb * Dd * Nn];
__device__ __align__(256) bf16 g_Wkh[Dd * Dd], g_Wkl[Dd * Dd];
__device__ __align__(256) bf16 g_Wqh[Dd * Dd], g_Wql[Dd * Dd];
__device__ __align__(256) bf16 g_Wvh[Dd * Dd], g_Wvl[Dd * Dd];
__device__ __align__(256) bf16 g_WoTh[Dd * Dd], g_WoTl[Dd * Dd];
__device__ __align__(256) bf16 g_WqkTh[Dd * Dd], g_WqkTl[Dd * Dd];
__device__ __align__(256) bf16 g_WvoTh[Dd * Dd], g_WvoTl[Dd * Dd];
__device__ __align__(256) bf16 g_miwh[3 * Dd * Dd], g_miwl[3 * Dd * Dd];
__device__ __align__(256) bf16 g_mowh[Dd * Dd], g_mowl[Dd * Dd];
__device__ __align__(256) bf16 g_W1Th[2 * Dd * Dd], g_W1Tl[2 * Dd * Dd];
__device__ __align__(256) bf16 g_W2Th[2 * Dd * Dd], g_W2Tl[2 * Dd * Dd];
__device__ __align__(256) bf16 g_snh[Bb * KS * Dd], g_snl[Bb * KS * Dd];
__device__ __align__(256) bf16 g_qh[Bb * KS * Dd], g_ql[Bb * KS * Dd];
__device__ __align__(256) bf16 g_awh[(size_t)Bb * KS * Nn], g_awl[(size_t)Bb * KS * Nn];
__device__ __align__(256) bf16 g_u1h[Bb * KS * Dd], g_u1l[Bb * KS * Dd];
__device__ __align__(256) bf16 g_slbh[Bb * KS * Dd], g_slbl[Bb * KS * Dd];
__device__ __align__(256) bf16 g_sah[Bb * KS * Dd], g_sal[Bb * KS * Dd];
__device__ __align__(256) bf16 g_hh[Bb * KS * Dd], g_hl[Bb * KS * Dd];
__device__ __align__(256) bf16 g_tbh[Bb * KS * 2 * Dd], g_tbl[Bb * KS * 2 * Dd];
// fp32
__device__ __align__(256) float g_slots[Bb * KS * Dd];
__device__ __align__(256) float g_attn[(size_t)Bb * KS * Nn];
__device__ __align__(256) float g_qkv[Bb * KS * 3 * Dd];
__device__ __align__(256) float g_P[Bb * Hh * KS * KS];
__device__ __align__(256) float g_tmp[Bb * KS * Dd];

__device__ __forceinline__ float gelu_exact(float x) {
    return 0.5f * x * (1.0f + erff(x * 0.7071067811865476f));
}
__device__ __forceinline__ void split1(float v, bf16& h, bf16& l) {
    h = __float2bfloat16(v);
    l = __float2bfloat16(v - __bfloat162float(h));
}

// ---------------- split kernels ----------------
__global__ void __launch_bounds__(256) split_k(const float* __restrict__ x,
                                               bf16* __restrict__ h, bf16* __restrict__ l) {
    int i = blockIdx.x * 256 + threadIdx.x;
    float4 v = ((const float4*)x)[i];
    bf16 h0, l0, h1, l1, h2, l2, h3, l3;
    split1(v.x, h0, l0); split1(v.y, h1, l1); split1(v.z, h2, l2); split1(v.w, h3, l3);
    ((bf162*)h)[2 * i]     = bf162(h0, h1);
    ((bf162*)h)[2 * i + 1] = bf162(h2, h3);
    ((bf162*)l)[2 * i]     = bf162(l0, l1);
    ((bf162*)l)[2 * i + 1] = bf162(l2, l3);
}

// transpose-split: fp32 [R,C] -> bf16 h/l [C,R]
__global__ void __launch_bounds__(256) tsplit_k(const float* __restrict__ x,
                                                bf16* __restrict__ h, bf16* __restrict__ l,
                                                int R, int C) {
    __shared__ float t[32][33];
    int c0 = blockIdx.x * 32, r0 = blockIdx.y * 32;
    int tid = threadIdx.x;
    int tr = tid >> 5, tc = tid & 31;
#pragma unroll
    for (int p = 0; p < 4; p++)
        t[tr + p * 8][tc] = x[(size_t)(r0 + tr + p * 8) * C + c0 + tc];
    __syncthreads();
#pragma unroll
    for (int p = 0; p < 4; p++) {
        int oc = tr + p * 8;
        float v = t[tc][oc];
        bf16 hh, ll;
        split1(v, hh, ll);
        h[(size_t)(c0 + oc) * R + r0 + tc] = hh;
        l[(size_t)(c0 + oc) * R + r0 + tc] = ll;
    }
}

// bf16 transpose of vn: [B][N][D] -> [B][D][N], both h and l arrays
__global__ void __launch_bounds__(256) vntrans_k(const bf16* __restrict__ ih,
                                                 const bf16* __restrict__ il,
                                                 bf16* __restrict__ oh,
                                                 bf16* __restrict__ ol) {
    int b = blockIdx.z;
    int d0 = blockIdx.x * 64, n0 = blockIdx.y * 64;
    const size_t ibase = (size_t)b * Nn * Dd;
    const size_t obase = (size_t)b * Dd * Nn;
    __shared__ bf16 th[64][65], tl[64][65];
    int tid = threadIdx.x;
#pragma unroll
    for (int p = 0; p < 16; p++) {
        int idx = tid + p * 256;
        int nr = idx >> 6, dc = idx & 63;
        th[nr][dc] = ih[ibase + (size_t)(n0 + nr) * Dd + d0 + dc];
        tl[nr][dc] = il[ibase + (size_t)(n0 + nr) * Dd + d0 + dc];
    }
    __syncthreads();
#pragma unroll
    for (int p = 0; p < 16; p++) {
        int idx = tid + p * 256;
        int dr = idx >> 6, nc = idx & 63;
        oh[obase + (size_t)(d0 + dr) * Nn + n0 + nc] = th[nc][dr];
        ol[obase + (size_t)(d0 + dr) * Nn + n0 + nc] = tl[nc][dr];
    }
}

// ---------------- LayerNorm: optional residual; outputs fp32 and/or split bf16 ----------------
__global__ void __launch_bounds__(256) ln_kernel(const float* __restrict__ x,
                                                 const float* __restrict__ res,
                                                 const float* __restrict__ gam,
                                                 const float* __restrict__ bet,
                                                 float* __restrict__ yf,
                                                 bf16* __restrict__ yh,
                                                 bf16* __restrict__ yl) {
    int row = blockIdx.x;
    int tid = threadIdx.x;
    float4 v = ((const float4*)(x + (size_t)row * Dd))[tid];
    if (res) {
        float4 r = ((const float4*)(res + (size_t)row * Dd))[tid];
        v.x += r.x; v.y += r.y; v.z += r.z; v.w += r.w;
    }
    float s  = v.x + v.y + v.z + v.w;
    float ss = v.x * v.x + v.y * v.y + v.z * v.z + v.w * v.w;
#pragma unroll
    for (int o = 16; o > 0; o >>= 1) {
        s  += __shfl_down_sync(0xffffffffu, s, o);
        ss += __shfl_down_sync(0xffffffffu, ss, o);
    }
    __shared__ float wsum[8], wsq[8];
    __shared__ float smean, srstd;
    int w = tid >> 5, l = tid & 31;
    if (l == 0) { wsum[w] = s; wsq[w] = ss; }
    __syncthreads();
    if (tid == 0) {
        float S = 0.f, SS = 0.f;
#pragma unroll
        for (int i = 0; i < 8; i++) { S += wsum[i]; SS += wsq[i]; }
        float mean = S * (1.0f / Dd);
        float var  = SS * (1.0f / Dd) - mean * mean;
        smean = mean;
        srstd = rsqrtf(var + 1e-5f);
    }
    __syncthreads();
    float mean = smean, rstd = srstd;
    float4 gg = ((const float4*)gam)[tid];
    float4 bb = ((const float4*)bet)[tid];
    float4 o;
    o.x = (v.x - mean) * rstd * gg.x + bb.x;
    o.y = (v.y - mean) * rstd * gg.y + bb.y;
    o.z = (v.z - mean) * rstd * gg.z + bb.z;
    o.w = (v.w - mean) * rstd * gg.w + bb.w;
    if (yf) ((float4*)(yf + (size_t)row * Dd))[tid] = o;
    if (yh) {
        bf16 h0, l0, h1, l1, h2, l2, h3, l3;
        split1(o.x, h0, l0); split1(o.y, h1, l1); split1(o.z, h2, l2); split1(o.w, h3, l3);
        bf162* hp = (bf162*)(yh + (size_t)row * Dd);
        bf162* lp = (bf162*)(yl + (size_t)row * Dd);
        hp[2 * tid] = bf162(h0, h1); hp[2 * tid + 1] = bf162(h2, h3);
        lp[2 * tid] = bf162(l0, l1); lp[2 * tid + 1] = bf162(l2, l3);
    }
}

__global__ void __launch_bounds__(256) bcast_slots(const float* __restrict__ si,
                                                   float* __restrict__ slots) {
    int idx = blockIdx.x * 256 + threadIdx.x;
    slots[idx] = si[idx & (KS * Dd - 1)];
}

// ---------------- softmax over SLOT axis of attn[B][K][N]; writes split bf16 aw ----------------
__global__ void __launch_bounds__(256) softmax_slots(const float* __restrict__ attn,
                                                     bf16* __restrict__ awh,
                                                     bf16* __restrict__ awl) {
    int idx = blockIdx.x * 256 + threadIdx.x;
    int b = idx >> 12;
    int n = idx & (Nn - 1);
    const float* p = attn + (size_t)b * KS * Nn + n;
    float m = -1e30f;
#pragma unroll 8
    for (int k = 0; k < KS; k++) m = fmaxf(m, p[(size_t)k * Nn]);
    float s = 0.f;
#pragma unroll 8
    for (int k = 0; k < KS; k++) s += expf(p[(size_t)k * Nn] - m);
    float inv = 1.0f / s;
    size_t base = (size_t)b * KS * Nn + n;
#pragma unroll 8
    for (int k = 0; k < KS; k++) {
        float e = expf(p[(size_t)k * Nn] - m) * inv;
        bf16 h, l;
        split1(e, h, l);
        awh[base + (size_t)k * Nn] = h;
        awl[base + (size_t)k * Nn] = l;
    }
}

// ---------------- MHA inner ----------------
__global__ void __launch_bounds__(256) mha_scores(const float* __restrict__ qkv,
                                                  float* __restrict__ P) {
    int bh = blockIdx.x;
    int b = bh / Hh, h = bh % Hh;
    const float* base = qkv + (size_t)b * KS * 3 * Dd;
    __shared__ float sk[KS][DHh + 1];
    int tid = threadIdx.x;
    for (int i = tid; i < KS * DHh; i += 256) {
        int kj = i >> 7, dd = i & 127;
        sk[kj][dd] = base[(size_t)kj * 3 * Dd + Dd + h * DHh + dd];
    }
    __syncthreads();
    int w = tid >> 5, lane = tid & 31;
    const float rsDH = 0.08838834764831845f;
    for (int r = 0; r < 8; r++) {
        int qi = w * 8 + r;
        const float* qrow = base + (size_t)qi * 3 * Dd + h * DHh;
        float s0 = 0.f, s1 = 0.f;
#pragma unroll 4
        for (int dd = 0; dd < DHh; dd++) {
            float qd = qrow[dd];
            s0 = fmaf(qd, sk[lane][dd], s0);
            s1 = fmaf(qd, sk[lane + 32][dd], s1);
        }
        s0 *= rsDH; s1 *= rsDH;
        float mx = fmaxf(s0, s1);
#pragma unroll
        for (int o = 16; o > 0; o >>= 1) mx = fmaxf(mx, __shfl_xor_sync(0xffffffffu, mx, o));
        float e0 = expf(s0 - mx), e1 = expf(s1 - mx);
        float sum = e0 + e1;
#pragma unroll
        for (int o = 16; o > 0; o >>= 1) sum += __shfl_xor_sync(0xffffffffu, sum, o);
        float inv = 1.0f / sum;
        P[(size_t)bh * 4096 + qi * 64 + lane]      = e0 * inv;
        P[(size_t)bh * 4096 + qi * 64 + lane + 32] = e1 * inv;
    }
}

__global__ void __launch_bounds__(256) mha_av(const float* __restrict__ qkv,
                                              const float* __restrict__ P,
                                              bf16* __restrict__ sah,
                                              bf16* __restrict__ sal) {
    int bh = blockIdx.x;
    int b = bh / Hh, h = bh % Hh;
    const float* vbase = qkv + (size_t)b * KS * 3 * Dd + 2 * Dd + h * DHh;
    __shared__ float sv[KS][DHh];
    __shared__ float sp[KS][KS];
    int tid = threadIdx.x;
    for (int i = tid; i < KS * DHh; i += 256) {
        int kj = i >> 7, dd = i & 127;
        sv[kj][dd] = vbase[(size_t)kj * 3 * Dd + dd];
    }
    for (int i = tid; i < KS * KS; i += 256)
        sp[i >> 6][i & 63] = P[(size_t)bh * 4096 + i];
    __syncthreads();
    int d = tid & 127;
    int half = tid >> 7;
    for (int j0 = 0; j0 < 32; j0 += 4) {
        int qi = half * 32 + j0;
        float a0 = 0.f, a1 = 0.f, a2 = 0.f, a3 = 0.f;
#pragma unroll 8
        for (int kj = 0; kj < KS; kj++) {
            float vv = sv[kj][d];
            a0 = fmaf(sp[qi][kj],     vv, a0);
            a1 = fmaf(sp[qi + 1][kj], vv, a1);
            a2 = fmaf(sp[qi + 2][kj], vv, a2);
            a3 = fmaf(sp[qi + 3][kj], vv, a3);
        }
        size_t o = (size_t)b * KS * Dd + (size_t)qi * Dd + h * DHh + d;
        bf16 h0, l0;
        split1(a0, h0, l0); sah[o] = h0;          sal[o] = l0;
        split1(a1, h0, l0); sah[o + Dd] = h0;     sal[o + Dd] = l0;
        split1(a2, h0, l0); sah[o + 2 * Dd] = h0; sal[o + 2 * Dd] = l0;
        split1(a3, h0, l0); sah[o + 3 * Dd] = h0; sal[o + 3 * Dd] = l0;
    }
}

// ================= NT GEMM: split-bf16 operands, cp.async double-buffered =================
// C[m,n] = alpha * sum_k (Ah+Al)[m,k] * (Bh+Bl)[n,k]  (3-term split, drop Al*Bl)
// A [M,K] k-contig bf16 pairs; B [N,K] k-contig bf16 pairs. BM=64, BN=128, BK=32.
#define SSTR 40          // bf16 per smem row (32 + 8 pad)
#define GSTG 15360       // bf16 per stage: (2*64 + 256) * 40

__device__ __forceinline__ void mma_bf16(float* d, const uint32_t* a, uint32_t b0, uint32_t b1) {
    asm volatile(
        "mma.sync.aligned.m16n8k16.row.col.f32.bf16.bf16.f32 "
        "{%0,%1,%2,%3}, {%4,%5,%6,%7}, {%8,%9}, {%0,%1,%2,%3};\n"
        : "+f"(d[0]), "+f"(d[1]), "+f"(d[2]), "+f"(d[3])
        : "r"(a[0]), "r"(a[1]), "r"(a[2]), "r"(a[3]), "r"(b0), "r"(b1));
}
__device__ __forceinline__ void cp16(bf16* s, const bf16* g) {
    uint32_t sa = (uint32_t)__cvta_generic_to_shared(s);
    asm volatile("cp.async.cg.shared.global [%0], [%1], 16;\n" :: "r"(sa), "l"(g));
}

__global__ void __launch_bounds__(256) gemm_nt(
    const bf16* __restrict__ Ah, const bf16* __restrict__ Al,
    const bf16* __restrict__ Bh, const bf16* __restrict__ Bl,
    int Kd, long long sA, long long sB,
    float alpha,
    float* __restrict__ Cf, int ldc, long long sC,
    bf16* __restrict__ Ch, bf16* __restrict__ Cl, int ldch, long long sCh,
    const float* __restrict__ bias,
    const float* __restrict__ add, int ldadd, long long sAdd,
    int act) {
    extern __shared__ __align__(16) bf16 sm_dyn[];

    int bz = blockIdx.z;
    Ah += bz * sA; Al += bz * sA;
    Bh += bz * sB; Bl += bz * sB;
    if (Cf) Cf += bz * sC;
    if (Ch) { Ch += bz * sCh; Cl += bz * sCh; }
    if (add) add += bz * sAdd;

    int bm = blockIdx.y * 64;
    int bn = blockIdx.x * 128;
    int tid = threadIdx.x, lane = tid & 31, wid = tid >> 5;
    int wm = (wid >> 2) * 32;
    int wn = (wid & 3) * 32;
    int r = lane >> 2, cc = lane & 3;

    float acc[2][4][4] = {};

    int ldrow = tid >> 2, ldc4 = tid & 3;      // A mapping (256 chunks)
    int brow0 = tid >> 2;                      // B first 64 rows? no: idx>>2 over 512

    // tile loader
    auto load_tile = [&](int s, int k0) {
        bf16* base = sm_dyn + s * GSTG;
        // A: 64 rows x 4 chunks = 256 chunks per array -> 1 per thread
        cp16(base + ldrow * SSTR + ldc4 * 8,        Ah + (size_t)(bm + ldrow) * Kd + k0 + ldc4 * 8);
        cp16(base + (64 + ldrow) * SSTR + ldc4 * 8, Al + (size_t)(bm + ldrow) * Kd + k0 + ldc4 * 8);
        // B: 128 rows x 4 chunks = 512 chunks per array -> 2 per thread
#pragma unroll
        for (int p = 0; p < 2; p++) {
            int idx = tid + p * 256;
            int row = idx >> 2, c4 = idx & 3;
            cp16(base + (128 + row) * SSTR + c4 * 8, Bh + (size_t)(bn + row) * Kd + k0 + c4 * 8);
            cp16(base + (256 + row) * SSTR + c4 * 8, Bl + (size_t)(bn + row) * Kd + k0 + c4 * 8);
        }
        asm volatile("cp.async.commit_group;\n");
    };

    int T = Kd / 32;
    load_tile(0, 0);
    for (int t = 0; t < T; t++) {
        if (t + 1 < T) {
            load_tile((t + 1) & 1, (t + 1) * 32);
            asm volatile("cp.async.wait_group 1;\n");
        } else {
            asm volatile("cp.async.wait_group 0;\n");
        }
        __syncthreads();
        const uint32_t* W = (const uint32_t*)(sm_dyn + (t & 1) * GSTG);
        const uint32_t* AhW = W;
        const uint32_t* AlW = W + 64 * 20;
        const uint32_t* BhW = W + 128 * 20;
        const uint32_t* BlW = W + 256 * 20;
#pragma unroll
        for (int s = 0; s < 2; s++) {
            int kb = s * 8;
            uint32_t ah[2][4], al[2][4], bh[4][2], bl[4][2];
#pragma unroll
            for (int ms = 0; ms < 2; ms++) {
                int b0 = (wm + ms * 16 + r) * 20 + kb + cc;
                int b8 = b0 + 8 * 20;
                ah[ms][0] = AhW[b0]; ah[ms][1] = AhW[b8];
                ah[ms][2] = AhW[b0 + 4]; ah[ms][3] = AhW[b8 + 4];
                al[ms][0] = AlW[b0]; al[ms][1] = AlW[b8];
                al[ms][2] = AlW[b0 + 4]; al[ms][3] = AlW[b8 + 4];
            }
#pragma unroll
            for (int ns = 0; ns < 4; ns++) {
                int nb = (wn + ns * 8 + r) * 20 + kb + cc;
                bh[ns][0] = BhW[nb]; bh[ns][1] = BhW[nb + 4];
                bl[ns][0] = BlW[nb]; bl[ns][1] = BlW[nb + 4];
            }
            // term-major ordering: consecutive MMAs hit different accumulators
#pragma unroll
            for (int ns = 0; ns < 4; ns++)
#pragma unroll
                for (int ms = 0; ms < 2; ms++)
                    mma_bf16(acc[ms][ns], ah[ms], bh[ns][0], bh[ns][1]);
#pragma unroll
            for (int ns = 0; ns < 4; ns++)
#pragma unroll
                for (int ms = 0; ms < 2; ms++)
                    mma_bf16(acc[ms][ns], ah[ms], bl[ns][0], bl[ns][1]);
#pragma unroll
            for (int ns = 0; ns < 4; ns++)
#pragma unroll
                for (int ms = 0; ms < 2; ms++)
                    mma_bf16(acc[ms][ns], al[ms], bh[ns][0], bh[ns][1]);
        }
        __syncthreads();
    }

    // epilogue
#pragma unroll
    for (int ms = 0; ms < 2; ms++) {
        int i0 = bm + wm + ms * 16 + r;
#pragma unroll
        for (int ns = 0; ns < 4; ns++) {
            int j = bn + wn + ns * 8 + 2 * cc;
            float v00 = acc[ms][ns][0] * alpha, v01 = acc[ms][ns][1] * alpha;
            float v10 = acc[ms][ns][2] * alpha, v11 = acc[ms][ns][3] * alpha;
            if (bias) {
                float bj0 = bias[j], bj1 = bias[j + 1];
                v00 += bj0; v01 += bj1; v10 += bj0; v11 += bj1;
            }
            if (act == 1) {
                v00 = gelu_exact(v00); v01 = gelu_exact(v01);
                v10 = gelu_exact(v10); v11 = gelu_exact(v11);
            }
            if (add) {
                v00 += add[(size_t)i0 * ldadd + j];
                v01 += add[(size_t)i0 * ldadd + j + 1];
                v10 += add[(size_t)(i0 + 8) * ldadd + j];
                v11 += add[(size_t)(i0 + 8) * ldadd + j + 1];
            }
            if (Cf) {
                float2 a2; a2.x = v00; a2.y = v01;
                float2 b2; b2.x = v10; b2.y = v11;
                *(float2*)(Cf + (size_t)i0 * ldc + j) = a2;
                *(float2*)(Cf + (size_t)(i0 + 8) * ldc + j) = b2;
            }
            if (Ch) {
                bf16 h00, l00, h01, l01, h10, l10, h11, l11;
                split1(v00, h00, l00); split1(v01, h01, l01);
                split1(v10, h10, l10); split1(v11, h11, l11);
                *(bf162*)(Ch + (size_t)i0 * ldch + j) = bf162(h00, h01);
                *(bf162*)(Cl + (size_t)i0 * ldch + j) = bf162(l00, l01);
                *(bf162*)(Ch + (size_t)(i0 + 8) * ldch + j) = bf162(h10, h11);
                *(bf162*)(Cl + (size_t)(i0 + 8) * ldch + j) = bf162(l10, l11);
            }
        }
    }
}

// ---------------- launcher ----------------
#define SYM(p, s) cudaGetSymbolAddress((void**)&p, s)

extern "C" void kernel_launch(void* const* d_in, const int* in_sizes, int n_in,
                              void* d_out, int out_size) {
    const float* vis       = (const float*)d_in[0];
    const float* slot_init = (const float*)d_in[1];
    const float* ln_vis_g  = (const float*)d_in[2];
    const float* ln_vis_b  = (const float*)d_in[3];
    const float* ln_sl_g   = (const float*)d_in[4];
    const float* ln_sl_b   = (const float*)d_in[5];
    const float* Wq        = (const float*)d_in[6];
    const float* Wk        = (const float*)d_in[7];
    const float* Wv        = (const float*)d_in[8];
    const float* Wo        = (const float*)d_in[9];
    const float* mha_in_w  = (const float*)d_in[10];
    const float* mha_in_b  = (const float*)d_in[11];
    const float* mha_out_w = (const float*)d_in[12];
    const float* mha_out_b = (const float*)d_in[13];
    const float* ln_sa_g   = (const float*)d_in[14];
    const float* ln_sa_b   = (const float*)d_in[15];
    const float* ln_ffn_g  = (const float*)d_in[16];
    const float* ln_ffn_b  = (const float*)d_in[17];
    const float* W1        = (const float*)d_in[18];
    const float* b1        = (const float*)d_in[19];
    const float* W2        = (const float*)d_in[20];
    const float* b2        = (const float*)d_in[21];

    bf16 *vnh, *vnl, *vnTh, *vnTl, *Wkh, *Wkl, *Wqh, *Wql, *Wvh, *Wvl, *WoTh, *WoTl;
    bf16 *WqkTh, *WqkTl, *WvoTh, *WvoTl, *miwh, *miwl, *mowh, *mowl;
    bf16 *W1Th, *W1Tl, *W2Th, *W2Tl, *snh, *snl, *qh, *ql, *awh, *awl;
    bf16 *u1h, *u1l, *slbh, *slbl, *sah, *sal, *hh, *hl, *tbh, *tbl;
    float *slots, *attn, *qkv, *P, *tmp;
    SYM(vnh, g_vnh); SYM(vnl, g_vnl); SYM(vnTh, g_vnTh); SYM(vnTl, g_vnTl);
    SYM(Wkh, g_Wkh); SYM(Wkl, g_Wkl); SYM(Wqh, g_Wqh); SYM(Wql, g_Wql);
    SYM(Wvh, g_Wvh); SYM(Wvl, g_Wvl); SYM(WoTh, g_WoTh); SYM(WoTl, g_WoTl);
    SYM(WqkTh, g_WqkTh); SYM(WqkTl, g_WqkTl); SYM(WvoTh, g_WvoTh); SYM(WvoTl, g_WvoTl);
    SYM(miwh, g_miwh); SYM(miwl, g_miwl); SYM(mowh, g_mowh); SYM(mowl, g_mowl);
    SYM(W1Th, g_W1Th); SYM(W1Tl, g_W1Tl); SYM(W2Th, g_W2Th); SYM(W2Tl, g_W2Tl);
    SYM(snh, g_snh); SYM(snl, g_snl); SYM(qh, g_qh); SYM(ql, g_ql);
    SYM(awh, g_awh); SYM(awl, g_awl); SYM(u1h, g_u1h); SYM(u1l, g_u1l);
    SYM(slbh, g_slbh); SYM(slbl, g_slbl); SYM(sah, g_sah); SYM(sal, g_sal);
    SYM(hh, g_hh); SYM(hl, g_hl); SYM(tbh, g_tbh); SYM(tbl, g_tbl);
    SYM(slots, g_slots); SYM(attn, g_attn); SYM(qkv, g_qkv); SYM(P, g_P); SYM(tmp, g_tmp);

    float* out = (float*)d_out;

    const int SMEM = 2 * GSTG * (int)sizeof(bf16);   // 61440
    cudaFuncSetAttribute(gemm_nt, cudaFuncAttributeMaxDynamicSharedMemorySize, SMEM);

    // ---- precompute: splits ----
    split_k<<<Dd * Dd / 1024, 256>>>(Wk, Wkh, Wkl);
    split_k<<<Dd * Dd / 1024, 256>>>(Wq, Wqh, Wql);
    split_k<<<Dd * Dd / 1024, 256>>>(Wv, Wvh, Wvl);
    split_k<<<3 * Dd * Dd / 1024, 256>>>(mha_in_w, miwh, miwl);
    split_k<<<Dd * Dd / 1024, 256>>>(mha_out_w, mowh, mowl);
    tsplit_k<<<dim3(Dd / 32, Dd / 32), 256>>>(Wo, WoTh, WoTl, Dd, Dd);
    tsplit_k<<<dim3(2 * Dd / 32, Dd / 32), 256>>>(W1, W1Th, W1Tl, Dd, 2 * Dd);
    tsplit_k<<<dim3(Dd / 32, 2 * Dd / 32), 256>>>(W2, W2Th, W2Tl, 2 * Dd, Dd);

    // vn = LN(visual_tokens) -> split bf16; then transpose
    ln_kernel<<<Bb * Nn, 256>>>(vis, nullptr, ln_vis_g, ln_vis_b, nullptr, vnh, vnl);
    vntrans_k<<<dim3(Dd / 64, Nn / 64, Bb), 256>>>(vnh, vnl, vnTh, vnTl);

    // WqkT = Wk @ Wq^T ; WvoT = WoT @ Wv^T   (both split-only outputs)
    gemm_nt<<<dim3(8, 16, 1), 256, SMEM>>>(Wkh, Wkl, Wqh, Wql, Dd, 0, 0, 1.0f,
        nullptr, 0, 0, WqkTh, WqkTl, Dd, 0, nullptr, nullptr, 0, 0, 0);
    gemm_nt<<<dim3(8, 16, 1), 256, SMEM>>>(WoTh, WoTl, Wvh, Wvl, Dd, 0, 0, 1.0f,
        nullptr, 0, 0, WvoTh, WvoTl, Dd, 0, nullptr, nullptr, 0, 0, 0);

    bcast_slots<<<(Bb * KS * Dd) / 256, 256>>>(slot_init, slots);

    const int Mfull = Bb * KS;  // 1024
    for (int it = 0; it < 2; it++) {
        // sn = LN(slots) -> split
        ln_kernel<<<Mfull, 256>>>(slots, nullptr, ln_sl_g, ln_sl_b, nullptr, snh, snl);
        // q = sn @ WqkT^T -> split
        gemm_nt<<<dim3(8, 16, 1), 256, SMEM>>>(snh, snl, WqkTh, WqkTl, Dd, 0, 0, 1.0f,
            nullptr, 0, 0, qh, ql, Dd, 0, nullptr, nullptr, 0, 0, 0);
        // attn[b] = (1/32) q[b] @ vn[b]^T -> fp32
        gemm_nt<<<dim3(32, 1, Bb), 256, SMEM>>>(qh, ql, vnh, vnl, Dd,
            (long long)KS * Dd, (long long)Nn * Dd, 0.03125f,
            attn, Nn, (long long)KS * Nn, nullptr, nullptr, 0, 0,
            nullptr, nullptr, 0, 0, 0);
        // aw = softmax over slot axis -> split
        softmax_slots<<<(Bb * Nn) / 256, 256>>>(attn, awh, awl);
        // u1[b] = aw[b] @ vnT[b]^T -> split
        gemm_nt<<<dim3(8, 1, Bb), 256, SMEM>>>(awh, awl, vnTh, vnTl, Nn,
            (long long)KS * Nn, (long long)Dd * Nn, 1.0f,
            nullptr, 0, 0, u1h, u1l, Dd, (long long)KS * Dd,
            nullptr, nullptr, 0, 0, 0);
        // slots = slots + u1 @ WvoT^T  -> fp32 + split
        gemm_nt<<<dim3(8, 16, 1), 256, SMEM>>>(u1h, u1l, WvoTh, WvoTl, Dd, 0, 0, 1.0f,
            slots, Dd, 0, slbh, slbl, Dd, 0, nullptr, slots, Dd, 0, 0);
        // qkv = slots @ mha_in_w^T + b -> fp32
        gemm_nt<<<dim3(24, 16, 1), 256, SMEM>>>(slbh, slbl, miwh, miwl, Dd, 0, 0, 1.0f,
            qkv, 3 * Dd, 0, nullptr, nullptr, 0, 0, mha_in_b, nullptr, 0, 0, 0);
        mha_scores<<<Bb * Hh, 256>>>(qkv, P);
        mha_av<<<Bb * Hh, 256>>>(qkv, P, sah, sal);
        // tmp = sa @ mha_out_w^T + b -> fp32
        gemm_nt<<<dim3(8, 16, 1), 256, SMEM>>>(sah, sal, mowh, mowl, Dd, 0, 0, 1.0f,
            tmp, Dd, 0, nullptr, nullptr, 0, 0, mha_out_b, nullptr, 0, 0, 0);
        // slots = LN(slots + tmp) -> fp32
        ln_kernel<<<Mfull, 256>>>(slots, tmp, ln_sa_g, ln_sa_b, slots, nullptr, nullptr);
    }

    // h = LN(slots) -> split
    ln_kernel<<<Mfull, 256>>>(slots, nullptr, ln_ffn_g, ln_ffn_b, nullptr, hh, hl);
    // tb = gelu(h @ W1T^T + b1) -> split
    gemm_nt<<<dim3(16, 16, 1), 256, SMEM>>>(hh, hl, W1Th, W1Tl, Dd, 0, 0, 1.0f,
        nullptr, 0, 0, tbh, tbl, 2 * Dd, 0, b1, nullptr, 0, 0, 1);
    // out = slots + tb @ W2T^T + b2 -> fp32
    gemm_nt<<<dim3(8, 16, 1), 256, SMEM>>>(tbh, tbl, W2Th, W2Tl, 2 * Dd, 0, 0, 1.0f,
        out, Dd, 0, nullptr, nullptr, 0, 0, b2, slots, Dd, 0, 0);
}

// round 5
// speedup vs baseline: 3.1430x; 1.1318x over previous
#include <cuda_runtime.h>
#include <cuda_bf16.h>
#include <cstdint>

#define Bb 16
#define Nn 4096
#define KS 64
#define Dd 1024
#define Hh 8
#define DHh 128

typedef __nv_bfloat16 bf16;
typedef __nv_bfloat162 bf162;

// ---------------- scratch (device globals) ----------------
__device__ __align__(256) bf16 g_vnh[(size_t)Bb * Nn * Dd];
__device__ __align__(256) bf16 g_vnl[(size_t)Bb * Nn * Dd];
__device__ __align__(256) bf16 g_Wkh[Dd * Dd], g_Wkl[Dd * Dd];
__device__ __align__(256) bf16 g_Wqh[Dd * Dd], g_Wql[Dd * Dd];
__device__ __align__(256) bf16 g_Wvh[Dd * Dd], g_Wvl[Dd * Dd];
__device__ __align__(256) bf16 g_Woh[Dd * Dd], g_Wol[Dd * Dd];
__device__ __align__(256) bf16 g_Wqkh[Dd * Dd], g_Wqkl[Dd * Dd];
__device__ __align__(256) bf16 g_Wvoh[Dd * Dd], g_Wvol[Dd * Dd];
__device__ __align__(256) bf16 g_miwh[3 * Dd * Dd], g_miwl[3 * Dd * Dd];
__device__ __align__(256) bf16 g_mowh[Dd * Dd], g_mowl[Dd * Dd];
__device__ __align__(256) bf16 g_W1h[2 * Dd * Dd], g_W1l[2 * Dd * Dd];
__device__ __align__(256) bf16 g_W2h[2 * Dd * Dd], g_W2l[2 * Dd * Dd];
__device__ __align__(256) bf16 g_snh[Bb * KS * Dd], g_snl[Bb * KS * Dd];
__device__ __align__(256) bf16 g_qh[Bb * KS * Dd], g_ql[Bb * KS * Dd];
__device__ __align__(256) bf16 g_awh[(size_t)Bb * KS * Nn], g_awl[(size_t)Bb * KS * Nn];
__device__ __align__(256) bf16 g_u1h[Bb * KS * Dd], g_u1l[Bb * KS * Dd];
__device__ __align__(256) bf16 g_slbh[Bb * KS * Dd], g_slbl[Bb * KS * Dd];
__device__ __align__(256) bf16 g_sah[Bb * KS * Dd], g_sal[Bb * KS * Dd];
__device__ __align__(256) bf16 g_hh[Bb * KS * Dd], g_hl[Bb * KS * Dd];
__device__ __align__(256) bf16 g_tbh[Bb * KS * 2 * Dd], g_tbl[Bb * KS * 2 * Dd];
__device__ __align__(256) float g_slots[Bb * KS * Dd];
__device__ __align__(256) float g_attn[(size_t)Bb * KS * Nn];
__device__ __align__(256) float g_qkv[Bb * KS * 3 * Dd];
__device__ __align__(256) float g_P[Bb * Hh * KS * KS];
__device__ __align__(256) float g_tmp[Bb * KS * Dd];

__device__ __forceinline__ float gelu_exact(float x) {
    return 0.5f * x * (1.0f + erff(x * 0.7071067811865476f));
}
__device__ __forceinline__ void split1(float v, bf16& h, bf16& l) {
    h = __float2bfloat16(v);
    l = __float2bfloat16(v - __bfloat162float(h));
}

// ---------------- merged weight split ----------------
struct SJ {
    const float* s[8];
    bf16* h[8];
    bf16* l[8];
    int cum[9];   // units of 1024-float blocks
};
__global__ void __launch_bounds__(256) split_all(SJ j) {
    int blk = blockIdx.x;
    int ti = 0;
#pragma unroll
    for (int i = 0; i < 7; i++) ti += (blk >= j.cum[i + 1]) ? 1 : 0;
    int idx = (blk - j.cum[ti]) * 256 + threadIdx.x;
    float4 v = ((const float4*)j.s[ti])[idx];
    bf16 h0, l0, h1, l1, h2, l2, h3, l3;
    split1(v.x, h0, l0); split1(v.y, h1, l1); split1(v.z, h2, l2); split1(v.w, h3, l3);
    ((bf162*)j.h[ti])[2 * idx]     = bf162(h0, h1);
    ((bf162*)j.h[ti])[2 * idx + 1] = bf162(h2, h3);
    ((bf162*)j.l[ti])[2 * idx]     = bf162(l0, l1);
    ((bf162*)j.l[ti])[2 * idx + 1] = bf162(l2, l3);
}

// ---------------- LayerNorm ----------------
__global__ void __launch_bounds__(256) ln_kernel(const float* __restrict__ x,
                                                 const float* __restrict__ res,
                                                 const float* __restrict__ gam,
                                                 const float* __restrict__ bet,
                                                 float* __restrict__ yf,
                                                 bf16* __restrict__ yh,
                                                 bf16* __restrict__ yl) {
    int row = blockIdx.x;
    int tid = threadIdx.x;
    float4 v = ((const float4*)(x + (size_t)row * Dd))[tid];
    if (res) {
        float4 r = ((const float4*)(res + (size_t)row * Dd))[tid];
        v.x += r.x; v.y += r.y; v.z += r.z; v.w += r.w;
    }
    float s  = v.x + v.y + v.z + v.w;
    float ss = v.x * v.x + v.y * v.y + v.z * v.z + v.w * v.w;
#pragma unroll
    for (int o = 16; o > 0; o >>= 1) {
        s  += __shfl_down_sync(0xffffffffu, s, o);
        ss += __shfl_down_sync(0xffffffffu, ss, o);
    }
    __shared__ float wsum[8], wsq[8];
    __shared__ float smean, srstd;
    int w = tid >> 5, l = tid & 31;
    if (l == 0) { wsum[w] = s; wsq[w] = ss; }
    __syncthreads();
    if (tid == 0) {
        float S = 0.f, SS = 0.f;
#pragma unroll
        for (int i = 0; i < 8; i++) { S += wsum[i]; SS += wsq[i]; }
        float mean = S * (1.0f / Dd);
        float var  = SS * (1.0f / Dd) - mean * mean;
        smean = mean;
        srstd = rsqrtf(var + 1e-5f);
    }
    __syncthreads();
    float mean = smean, rstd = srstd;
    float4 gg = ((const float4*)gam)[tid];
    float4 bb = ((const float4*)bet)[tid];
    float4 o;
    o.x = (v.x - mean) * rstd * gg.x + bb.x;
    o.y = (v.y - mean) * rstd * gg.y + bb.y;
    o.z = (v.z - mean) * rstd * gg.z + bb.z;
    o.w = (v.w - mean) * rstd * gg.w + bb.w;
    if (yf) ((float4*)(yf + (size_t)row * Dd))[tid] = o;
    if (yh) {
        bf16 h0, l0, h1, l1, h2, l2, h3, l3;
        split1(o.x, h0, l0); split1(o.y, h1, l1); split1(o.z, h2, l2); split1(o.w, h3, l3);
        bf162* hp = (bf162*)(yh + (size_t)row * Dd);
        bf162* lp = (bf162*)(yl + (size_t)row * Dd);
        hp[2 * tid] = bf162(h0, h1); hp[2 * tid + 1] = bf162(h2, h3);
        lp[2 * tid] = bf162(l0, l1); lp[2 * tid + 1] = bf162(l2, l3);
    }
}

__global__ void __launch_bounds__(256) bcast_slots(const float* __restrict__ si,
                                                   float* __restrict__ slots) {
    int idx = blockIdx.x * 256 + threadIdx.x;
    slots[idx] = si[idx & (KS * Dd - 1)];
}

// ---------------- softmax over SLOT axis ----------------
__global__ void __launch_bounds__(256) softmax_slots(const float* __restrict__ attn,
                                                     bf16* __restrict__ awh,
                                                     bf16* __restrict__ awl) {
    int idx = blockIdx.x * 256 + threadIdx.x;
    int b = idx >> 12;
    int n = idx & (Nn - 1);
    const float* p = attn + (size_t)b * KS * Nn + n;
    float m = -1e30f;
#pragma unroll 8
    for (int k = 0; k < KS; k++) m = fmaxf(m, p[(size_t)k * Nn]);
    float s = 0.f;
#pragma unroll 8
    for (int k = 0; k < KS; k++) s += expf(p[(size_t)k * Nn] - m);
    float inv = 1.0f / s;
    size_t base = (size_t)b * KS * Nn + n;
#pragma unroll 8
    for (int k = 0; k < KS; k++) {
        float e = expf(p[(size_t)k * Nn] - m) * inv;
        bf16 h, l;
        split1(e, h, l);
        awh[base + (size_t)k * Nn] = h;
        awl[base + (size_t)k * Nn] = l;
    }
}

// ---------------- MHA inner ----------------
__global__ void __launch_bounds__(256) mha_scores(const float* __restrict__ qkv,
                                                  float* __restrict__ P) {
    int bh = blockIdx.x;
    int b = bh / Hh, h = bh % Hh;
    const float* base = qkv + (size_t)b * KS * 3 * Dd;
    __shared__ float sk[KS][DHh + 1];
    int tid = threadIdx.x;
    for (int i = tid; i < KS * DHh; i += 256) {
        int kj = i >> 7, dd = i & 127;
        sk[kj][dd] = base[(size_t)kj * 3 * Dd + Dd + h * DHh + dd];
    }
    __syncthreads();
    int w = tid >> 5, lane = tid & 31;
    const float rsDH = 0.08838834764831845f;
    for (int r = 0; r < 8; r++) {
        int qi = w * 8 + r;
        const float* qrow = base + (size_t)qi * 3 * Dd + h * DHh;
        float s0 = 0.f, s1 = 0.f;
#pragma unroll 4
        for (int dd = 0; dd < DHh; dd++) {
            float qd = qrow[dd];
            s0 = fmaf(qd, sk[lane][dd], s0);
            s1 = fmaf(qd, sk[lane + 32][dd], s1);
        }
        s0 *= rsDH; s1 *= rsDH;
        float mx = fmaxf(s0, s1);
#pragma unroll
        for (int o = 16; o > 0; o >>= 1) mx = fmaxf(mx, __shfl_xor_sync(0xffffffffu, mx, o));
        float e0 = expf(s0 - mx), e1 = expf(s1 - mx);
        float sum = e0 + e1;
#pragma unroll
        for (int o = 16; o > 0; o >>= 1) sum += __shfl_xor_sync(0xffffffffu, sum, o);
        float inv = 1.0f / sum;
        P[(size_t)bh * 4096 + qi * 64 + lane]      = e0 * inv;
        P[(size_t)bh * 4096 + qi * 64 + lane + 32] = e1 * inv;
    }
}

__global__ void __launch_bounds__(256) mha_av(const float* __restrict__ qkv,
                                              const float* __restrict__ P,
                                              bf16* __restrict__ sah,
                                              bf16* __restrict__ sal) {
    int bh = blockIdx.x;
    int b = bh / Hh, h = bh % Hh;
    const float* vbase = qkv + (size_t)b * KS * 3 * Dd + 2 * Dd + h * DHh;
    __shared__ float sv[KS][DHh];
    __shared__ float sp[KS][KS];
    int tid = threadIdx.x;
    for (int i = tid; i < KS * DHh; i += 256) {
        int kj = i >> 7, dd = i & 127;
        sv[kj][dd] = vbase[(size_t)kj * 3 * Dd + dd];
    }
    for (int i = tid; i < KS * KS; i += 256)
        sp[i >> 6][i & 63] = P[(size_t)bh * 4096 + i];
    __syncthreads();
    int d = tid & 127;
    int half = tid >> 7;
    for (int j0 = 0; j0 < 32; j0 += 4) {
        int qi = half * 32 + j0;
        float a0 = 0.f, a1 = 0.f, a2 = 0.f, a3 = 0.f;
#pragma unroll 8
        for (int kj = 0; kj < KS; kj++) {
            float vv = sv[kj][d];
            a0 = fmaf(sp[qi][kj],     vv, a0);
            a1 = fmaf(sp[qi + 1][kj], vv, a1);
            a2 = fmaf(sp[qi + 2][kj], vv, a2);
            a3 = fmaf(sp[qi + 3][kj], vv, a3);
        }
        size_t o = (size_t)b * KS * Dd + (size_t)qi * Dd + h * DHh + d;
        bf16 h0, l0;
        split1(a0, h0, l0); sah[o] = h0;          sal[o] = l0;
        split1(a1, h0, l0); sah[o + Dd] = h0;     sal[o + Dd] = l0;
        split1(a2, h0, l0); sah[o + 2 * Dd] = h0; sal[o + 2 * Dd] = l0;
        split1(a3, h0, l0); sah[o + 3 * Dd] = h0; sal[o + 3 * Dd] = l0;
    }
}

// ================= split-bf16 GEMM: ldmatrix + 3-stage cp.async =================
// TB=true:  C = alpha*A@B^T, B [n][k] k-contig (NT)
// TB=false: C = alpha*A@B,   B [k][n] n-contig (NN, ldmatrix.trans)
// BM=64, BN=128, BK=32, 256 threads (8 warps, warp tile 32x32)

__device__ __forceinline__ void mma_bf16(float* d, const uint32_t* a, uint32_t b0, uint32_t b1) {
    asm volatile(
        "mma.sync.aligned.m16n8k16.row.col.f32.bf16.bf16.f32 "
        "{%0,%1,%2,%3}, {%4,%5,%6,%7}, {%8,%9}, {%0,%1,%2,%3};\n"
        : "+f"(d[0]), "+f"(d[1]), "+f"(d[2]), "+f"(d[3])
        : "r"(a[0]), "r"(a[1]), "r"(a[2]), "r"(a[3]), "r"(b0), "r"(b1));
}
__device__ __forceinline__ void cp16(bf16* s, const bf16* g) {
    uint32_t sa = (uint32_t)__cvta_generic_to_shared(s);
    asm volatile("cp.async.cg.shared.global [%0], [%1], 16;\n" :: "r"(sa), "l"(g));
}
#define LDSM4(r0, r1, r2, r3, a) \
    asm volatile("ldmatrix.sync.aligned.m8n8.x4.shared.b16 {%0,%1,%2,%3}, [%4];\n" \
                 : "=r"(r0), "=r"(r1), "=r"(r2), "=r"(r3) : "r"(a))
#define LDSM4T(r0, r1, r2, r3, a) \
    asm volatile("ldmatrix.sync.aligned.m8n8.x4.trans.shared.b16 {%0,%1,%2,%3}, [%4];\n" \
                 : "=r"(r0), "=r"(r1), "=r"(r2), "=r"(r3) : "r"(a))

template <bool TB>
__global__ void __launch_bounds__(256) gemm2(
    const bf16* __restrict__ Ah, const bf16* __restrict__ Al,
    const bf16* __restrict__ Bh, const bf16* __restrict__ Bl,
    int Kd, int ldb, long long sA, long long sB, float alpha,
    float* __restrict__ Cf, int ldc, long long sC,
    bf16* __restrict__ Ch, bf16* __restrict__ Cl, int ldch, long long sCh,
    const float* __restrict__ bias,
    const float* __restrict__ add, int ldadd, long long sAdd, int act) {
    constexpr int STG = TB ? 15360 : 13824;   // bf16 per stage
    constexpr int BOF = 5120;                 // B-hi offset
    constexpr int BLO = TB ? 10240 : 9472;    // B-lo offset
    extern __shared__ __align__(16) bf16 sm[];

    int bz = blockIdx.z;
    Ah += bz * sA; Al += bz * sA;
    Bh += bz * sB; Bl += bz * sB;
    if (Cf) Cf += bz * sC;
    if (Ch) { Ch += bz * sCh; Cl += bz * sCh; }
    if (add) add += bz * sAdd;

    int bm = blockIdx.y * 64;
    int bn = blockIdx.x * 128;
    int tid = threadIdx.x, lane = tid & 31, wid = tid >> 5;
    int wm = (wid >> 2) * 32;
    int wn = (wid & 3) * 32;
    int r = lane >> 2, cc = lane & 3;
    int arow = lane & 15, ahalf = lane >> 4;

    float acc[2][4][4] = {};

    int aw_r = tid >> 2, aw_c = tid & 3;

    auto load_tile = [&](int st, int k0) {
        bf16* s = sm + st * STG;
        cp16(s + aw_r * 40 + aw_c * 8,        Ah + (size_t)(bm + aw_r) * Kd + k0 + aw_c * 8);
        cp16(s + 2560 + aw_r * 40 + aw_c * 8, Al + (size_t)(bm + aw_r) * Kd + k0 + aw_c * 8);
        if (TB) {
#pragma unroll
            for (int p = 0; p < 2; p++) {
                int idx = tid + p * 256;
                int row = idx >> 2, c4 = idx & 3;
                cp16(s + BOF + row * 40 + c4 * 8, Bh + (size_t)(bn + row) * ldb + k0 + c4 * 8);
                cp16(s + BLO + row * 40 + c4 * 8, Bl + (size_t)(bn + row) * ldb + k0 + c4 * 8);
            }
        } else {
#pragma unroll
            for (int p = 0; p < 2; p++) {
                int idx = tid + p * 256;
                int row = idx >> 4, ch = idx & 15;
                cp16(s + BOF + row * 136 + ch * 8, Bh + (size_t)(k0 + row) * ldb + bn + ch * 8);
                cp16(s + BLO + row * 136 + ch * 8, Bl + (size_t)(k0 + row) * ldb + bn + ch * 8);
            }
        }
        asm volatile("cp.async.commit_group;\n");
    };

    int T = Kd / 32;
    load_tile(0, 0);
    load_tile(1, 32);

    uint32_t smem_base = (uint32_t)__cvta_generic_to_shared(sm);

    for (int t = 0; t < T; t++) {
        if (t + 1 < T) asm volatile("cp.async.wait_group 1;\n");
        else           asm volatile("cp.async.wait_group 0;\n");
        __syncthreads();
        if (t + 2 < T) {
            int st = t + 2; st -= (st / 3) * 3;
            load_tile(st, (t + 2) * 32);
        }
        int cst = t - (t / 3) * 3;
        uint32_t base = smem_base + cst * STG * 2;
#pragma unroll
        for (int s = 0; s < 2; s++) {
            uint32_t ah[2][4], al[2][4], bh[4][2], bl[4][2];
#pragma unroll
            for (int ms = 0; ms < 2; ms++) {
                uint32_t ad = base + ((wm + ms * 16 + arow) * 40 + s * 16 + ahalf * 8) * 2;
                LDSM4(ah[ms][0], ah[ms][1], ah[ms][2], ah[ms][3], ad);
                LDSM4(al[ms][0], al[ms][1], al[ms][2], al[ms][3], ad + 2560 * 2);
            }
            if (TB) {
#pragma unroll
                for (int pp = 0; pp < 2; pp++) {
                    uint32_t bd = base + (BOF + (wn + pp * 16 + arow) * 40 + s * 16 + ahalf * 8) * 2;
                    uint32_t r0, r1, r2, r3;
                    LDSM4(r0, r1, r2, r3, bd);
                    bh[2 * pp][0] = r0; bh[2 * pp + 1][0] = r1;
                    bh[2 * pp][1] = r2; bh[2 * pp + 1][1] = r3;
                    LDSM4(r0, r1, r2, r3, bd + (BLO - BOF) * 2);
                    bl[2 * pp][0] = r0; bl[2 * pp + 1][0] = r1;
                    bl[2 * pp][1] = r2; bl[2 * pp + 1][1] = r3;
                }
            } else {
#pragma unroll
                for (int pp = 0; pp < 2; pp++) {
                    uint32_t bd = base + (BOF + (s * 16 + arow) * 136 + wn + pp * 16 + ahalf * 8) * 2;
                    uint32_t r0, r1, r2, r3;
                    LDSM4T(r0, r1, r2, r3, bd);
                    bh[2 * pp][0] = r0; bh[2 * pp][1] = r1;
                    bh[2 * pp + 1][0] = r2; bh[2 * pp + 1][1] = r3;
                    LDSM4T(r0, r1, r2, r3, bd + (BLO - BOF) * 2);
                    bl[2 * pp][0] = r0; bl[2 * pp][1] = r1;
                    bl[2 * pp + 1][0] = r2; bl[2 * pp + 1][1] = r3;
                }
            }
            // term-major: consecutive MMAs hit different accumulators
#pragma unroll
            for (int ns = 0; ns < 4; ns++)
#pragma unroll
                for (int ms = 0; ms < 2; ms++)
                    mma_bf16(acc[ms][ns], ah[ms], bh[ns][0], bh[ns][1]);
#pragma unroll
            for (int ns = 0; ns < 4; ns++)
#pragma unroll
                for (int ms = 0; ms < 2; ms++)
                    mma_bf16(acc[ms][ns], ah[ms], bl[ns][0], bl[ns][1]);
#pragma unroll
            for (int ns = 0; ns < 4; ns++)
#pragma unroll
                for (int ms = 0; ms < 2; ms++)
                    mma_bf16(acc[ms][ns], al[ms], bh[ns][0], bh[ns][1]);
        }
    }

    // epilogue
#pragma unroll
    for (int ms = 0; ms < 2; ms++) {
        int i0 = bm + wm + ms * 16 + r;
#pragma unroll
        for (int ns = 0; ns < 4; ns++) {
            int j = bn + wn + ns * 8 + 2 * cc;
            float v00 = acc[ms][ns][0] * alpha, v01 = acc[ms][ns][1] * alpha;
            float v10 = acc[ms][ns][2] * alpha, v11 = acc[ms][ns][3] * alpha;
            if (bias) {
                float bj0 = bias[j], bj1 = bias[j + 1];
                v00 += bj0; v01 += bj1; v10 += bj0; v11 += bj1;
            }
            if (act == 1) {
                v00 = gelu_exact(v00); v01 = gelu_exact(v01);
                v10 = gelu_exact(v10); v11 = gelu_exact(v11);
            }
            if (add) {
                v00 += add[(size_t)i0 * ldadd + j];
                v01 += add[(size_t)i0 * ldadd + j + 1];
                v10 += add[(size_t)(i0 + 8) * ldadd + j];
                v11 += add[(size_t)(i0 + 8) * ldadd + j + 1];
            }
            if (Cf) {
                float2 a2; a2.x = v00; a2.y = v01;
                float2 b2; b2.x = v10; b2.y = v11;
                *(float2*)(Cf + (size_t)i0 * ldc + j) = a2;
                *(float2*)(Cf + (size_t)(i0 + 8) * ldc + j) = b2;
            }
            if (Ch) {
                bf16 h00, l00, h01, l01, h10, l10, h11, l11;
                split1(v00, h00, l00); split1(v01, h01, l01);
                split1(v10, h10, l10); split1(v11, h11, l11);
                *(bf162*)(Ch + (size_t)i0 * ldch + j) = bf162(h00, h01);
                *(bf162*)(Cl + (size_t)i0 * ldch + j) = bf162(l00, l01);
                *(bf162*)(Ch + (size_t)(i0 + 8) * ldch + j) = bf162(h10, h11);
                *(bf162*)(Cl + (size_t)(i0 + 8) * ldch + j) = bf162(l10, l11);
            }
        }
    }
}

// ---------------- launcher ----------------
#define SYM(p, s) cudaGetSymbolAddress((void**)&p, s)

extern "C" void kernel_launch(void* const* d_in, const int* in_sizes, int n_in,
                              void* d_out, int out_size) {
    const float* vis       = (const float*)d_in[0];
    const float* slot_init = (const float*)d_in[1];
    const float* ln_vis_g  = (const float*)d_in[2];
    const float* ln_vis_b  = (const float*)d_in[3];
    const float* ln_sl_g   = (const float*)d_in[4];
    const float* ln_sl_b   = (const float*)d_in[5];
    const float* Wq        = (const float*)d_in[6];
    const float* Wk        = (const float*)d_in[7];
    const float* Wv        = (const float*)d_in[8];
    const float* Wo        = (const float*)d_in[9];
    const float* mha_in_w  = (const float*)d_in[10];
    const float* mha_in_b  = (const float*)d_in[11];
    const float* mha_out_w = (const float*)d_in[12];
    const float* mha_out_b = (const float*)d_in[13];
    const float* ln_sa_g   = (const float*)d_in[14];
    const float* ln_sa_b   = (const float*)d_in[15];
    const float* ln_ffn_g  = (const float*)d_in[16];
    const float* ln_ffn_b  = (const float*)d_in[17];
    const float* W1        = (const float*)d_in[18];
    const float* b1        = (const float*)d_in[19];
    const float* W2        = (const float*)d_in[20];
    const float* b2        = (const float*)d_in[21];

    bf16 *vnh, *vnl, *Wkh, *Wkl, *Wqh, *Wql, *Wvh, *Wvl, *Woh, *Wol;
    bf16 *Wqkh, *Wqkl, *Wvoh, *Wvol, *miwh, *miwl, *mowh, *mowl;
    bf16 *W1h, *W1l, *W2h, *W2l, *snh, *snl, *qh, *ql, *awh, *awl;
    bf16 *u1h, *u1l, *slbh, *slbl, *sah, *sal, *hh, *hl, *tbh, *tbl;
    float *slots, *attn, *qkv, *P, *tmp;
    SYM(vnh, g_vnh); SYM(vnl, g_vnl);
    SYM(Wkh, g_Wkh); SYM(Wkl, g_Wkl); SYM(Wqh, g_Wqh); SYM(Wql, g_Wql);
    SYM(Wvh, g_Wvh); SYM(Wvl, g_Wvl); SYM(Woh, g_Woh); SYM(Wol, g_Wol);
    SYM(Wqkh, g_Wqkh); SYM(Wqkl, g_Wqkl); SYM(Wvoh, g_Wvoh); SYM(Wvol, g_Wvol);
    SYM(miwh, g_miwh); SYM(miwl, g_miwl); SYM(mowh, g_mowh); SYM(mowl, g_mowl);
    SYM(W1h, g_W1h); SYM(W1l, g_W1l); SYM(W2h, g_W2h); SYM(W2l, g_W2l);
    SYM(snh, g_snh); SYM(snl, g_snl); SYM(qh, g_qh); SYM(ql, g_ql);
    SYM(awh, g_awh); SYM(awl, g_awl); SYM(u1h, g_u1h); SYM(u1l, g_u1l);
    SYM(slbh, g_slbh); SYM(slbl, g_slbl); SYM(sah, g_sah); SYM(sal, g_sal);
    SYM(hh, g_hh); SYM(hl, g_hl); SYM(tbh, g_tbh); SYM(tbl, g_tbl);
    SYM(slots, g_slots); SYM(attn, g_attn); SYM(qkv, g_qkv); SYM(P, g_P); SYM(tmp, g_tmp);

    float* out = (float*)d_out;

    const int SM_NT = 3 * 15360 * 2;   // 92160
    const int SM_NN = 3 * 13824 * 2;   // 82944
    cudaFuncSetAttribute(gemm2<true>,  cudaFuncAttributeMaxDynamicSharedMemorySize, SM_NT);
    cudaFuncSetAttribute(gemm2<false>, cudaFuncAttributeMaxDynamicSharedMemorySize, SM_NN);

    // ---- merged weight split: Wq,Wk,Wv,Wo,mow (1M), miw (3M), W1 (2M), W2 (2M) ----
    {
        SJ j;
        j.s[0] = Wq;  j.h[0] = Wqh;  j.l[0] = Wql;
        j.s[1] = Wk;  j.h[1] = Wkh;  j.l[1] = Wkl;
        j.s[2] = Wv;  j.h[2] = Wvh;  j.l[2] = Wvl;
        j.s[3] = Wo;  j.h[3] = Woh;  j.l[3] = Wol;
        j.s[4] = mha_out_w; j.h[4] = mowh; j.l[4] = mowl;
        j.s[5] = mha_in_w;  j.h[5] = miwh; j.l[5] = miwl;
        j.s[6] = W1;  j.h[6] = W1h;  j.l[6] = W1l;
        j.s[7] = W2;  j.h[7] = W2h;  j.l[7] = W2l;
        int blocks[8] = {1024, 1024, 1024, 1024, 1024, 3072, 2048, 2048};
        j.cum[0] = 0;
        for (int i = 0; i < 8; i++) j.cum[i + 1] = j.cum[i] + blocks[i];
        split_all<<<j.cum[8], 256>>>(j);
    }

    // vn = LN(visual_tokens) -> split bf16 only
    ln_kernel<<<Bb * Nn, 256>>>(vis, nullptr, ln_vis_g, ln_vis_b, nullptr, vnh, vnl);

    // Wqk = Wq @ Wk^T (NT) -> split ; Wvo = Wv @ Wo (NN) -> split
    gemm2<true><<<dim3(8, 16, 1), 256, SM_NT>>>(Wqh, Wql, Wkh, Wkl, Dd, Dd, 0, 0, 1.0f,
        nullptr, 0, 0, Wqkh, Wqkl, Dd, 0, nullptr, nullptr, 0, 0, 0);
    gemm2<false><<<dim3(8, 16, 1), 256, SM_NN>>>(Wvh, Wvl, Woh, Wol, Dd, Dd, 0, 0, 1.0f,
        nullptr, 0, 0, Wvoh, Wvol, Dd, 0, nullptr, nullptr, 0, 0, 0);

    bcast_slots<<<(Bb * KS * Dd) / 256, 256>>>(slot_init, slots);

    const int Mfull = Bb * KS;  // 1024
    for (int it = 0; it < 2; it++) {
        ln_kernel<<<Mfull, 256>>>(slots, nullptr, ln_sl_g, ln_sl_b, nullptr, snh, snl);
        // q = sn @ Wqk  (NN)
        gemm2<false><<<dim3(8, 16, 1), 256, SM_NN>>>(snh, snl, Wqkh, Wqkl, Dd, Dd, 0, 0, 1.0f,
            nullptr, 0, 0, qh, ql, Dd, 0, nullptr, nullptr, 0, 0, 0);
        // attn[b] = (1/32) q[b] @ vn[b]^T  (NT)
        gemm2<true><<<dim3(32, 1, Bb), 256, SM_NT>>>(qh, ql, vnh, vnl, Dd, Dd,
            (long long)KS * Dd, (long long)Nn * Dd, 0.03125f,
            attn, Nn, (long long)KS * Nn, nullptr, nullptr, 0, 0,
            nullptr, nullptr, 0, 0, 0);
        softmax_slots<<<(Bb * Nn) / 256, 256>>>(attn, awh, awl);
        // u1[b] = aw[b] @ vn[b]  (NN — ldmatrix.trans, no vnT needed)
        gemm2<false><<<dim3(8, 1, Bb), 256, SM_NN>>>(awh, awl, vnh, vnl, Nn, Dd,
            (long long)KS * Nn, (long long)Nn * Dd, 1.0f,
            nullptr, 0, 0, u1h, u1l, Dd, (long long)KS * Dd,
            nullptr, nullptr, 0, 0, 0);
        // slots = slots + u1 @ Wvo  (NN) -> fp32 + split
        gemm2<false><<<dim3(8, 16, 1), 256, SM_NN>>>(u1h, u1l, Wvoh, Wvol, Dd, Dd, 0, 0, 1.0f,
            slots, Dd, 0, slbh, slbl, Dd, 0, nullptr, slots, Dd, 0, 0);
        // qkv = slots @ mha_in_w^T + b  (NT)
        gemm2<true><<<dim3(24, 16, 1), 256, SM_NT>>>(slbh, slbl, miwh, miwl, Dd, Dd, 0, 0, 1.0f,
            qkv, 3 * Dd, 0, nullptr, nullptr, 0, 0, mha_in_b, nullptr, 0, 0, 0);
        mha_scores<<<Bb * Hh, 256>>>(qkv, P);
        mha_av<<<Bb * Hh, 256>>>(qkv, P, sah, sal);
        // tmp = sa @ mha_out_w^T + b  (NT)
        gemm2<true><<<dim3(8, 16, 1), 256, SM_NT>>>(sah, sal, mowh, mowl, Dd, Dd, 0, 0, 1.0f,
            tmp, Dd, 0, nullptr, nullptr, 0, 0, mha_out_b, nullptr, 0, 0, 0);
        ln_kernel<<<Mfull, 256>>>(slots, tmp, ln_sa_g, ln_sa_b, slots, nullptr, nullptr);
    }

    ln_kernel<<<Mfull, 256>>>(slots, nullptr, ln_ffn_g, ln_ffn_b, nullptr, hh, hl);
    // tb = gelu(h @ W1 + b1)  (NN)
    gemm2<false><<<dim3(16, 16, 1), 256, SM_NN>>>(hh, hl, W1h, W1l, Dd, 2 * Dd, 0, 0, 1.0f,
        nullptr, 0, 0, tbh, tbl, 2 * Dd, 0, b1, nullptr, 0, 0, 1);
    // out = slots + tb @ W2 + b2  (NN)
    gemm2<false><<<dim3(8, 16, 1), 256, SM_NN>>>(tbh, tbl, W2h, W2l, 2 * Dd, Dd, 0, 0, 1.0f,
        out, Dd, 0, nullptr, nullptr, 0, 0, b2, slots, Dd, 0, 0);
}

// round 7
// speedup vs baseline: 3.4385x; 1.0940x over previous
#include <cuda_runtime.h>
#include <cuda_bf16.h>
#include <cstdint>

#define Bb 16
#define Nn 4096
#define KS 64
#define Dd 1024
#define Hh 8
#define DHh 128

typedef __nv_bfloat16 bf16;
typedef __nv_bfloat162 bf162;

// ---------------- scratch (device globals) ----------------
__device__ __align__(256) bf16 g_vnh[(size_t)Bb * Nn * Dd];
__device__ __align__(256) bf16 g_vnl[(size_t)Bb * Nn * Dd];
__device__ __align__(256) bf16 g_Wkh[Dd * Dd], g_Wkl[Dd * Dd];
__device__ __align__(256) bf16 g_Wqh[Dd * Dd], g_Wql[Dd * Dd];
__device__ __align__(256) bf16 g_Wvh[Dd * Dd], g_Wvl[Dd * Dd];
__device__ __align__(256) bf16 g_Woh[Dd * Dd], g_Wol[Dd * Dd];
__device__ __align__(256) bf16 g_Wqkh[Dd * Dd], g_Wqkl[Dd * Dd];
__device__ __align__(256) bf16 g_Wvoh[Dd * Dd], g_Wvol[Dd * Dd];
__device__ __align__(256) bf16 g_miwh[3 * Dd * Dd], g_miwl[3 * Dd * Dd];
__device__ __align__(256) bf16 g_mowh[Dd * Dd], g_mowl[Dd * Dd];
__device__ __align__(256) bf16 g_W1h[2 * Dd * Dd], g_W1l[2 * Dd * Dd];
__device__ __align__(256) bf16 g_W2h[2 * Dd * Dd], g_W2l[2 * Dd * Dd];
__device__ __align__(256) bf16 g_snh[Bb * KS * Dd], g_snl[Bb * KS * Dd];
__device__ __align__(256) bf16 g_qh[Bb * KS * Dd], g_ql[Bb * KS * Dd];
__device__ __align__(256) bf16 g_awh[(size_t)Bb * KS * Nn], g_awl[(size_t)Bb * KS * Nn];
__device__ __align__(256) bf16 g_u1h[Bb * KS * Dd], g_u1l[Bb * KS * Dd];
__device__ __align__(256) bf16 g_slbh[Bb * KS * Dd], g_slbl[Bb * KS * Dd];
__device__ __align__(256) bf16 g_sah[Bb * KS * Dd], g_sal[Bb * KS * Dd];
__device__ __align__(256) bf16 g_hh[Bb * KS * Dd], g_hl[Bb * KS * Dd];
__device__ __align__(256) bf16 g_tbh[Bb * KS * 2 * Dd], g_tbl[Bb * KS * 2 * Dd];
__device__ __align__(256) float g_slots[Bb * KS * Dd];
__device__ __align__(256) float g_attn[(size_t)Bb * KS * Nn];
__device__ __align__(256) float g_qkv[Bb * KS * 3 * Dd];
__device__ __align__(256) float g_P[Bb * Hh * KS * KS];
__device__ __align__(256) float g_tmp[Bb * KS * Dd];

__device__ __forceinline__ float gelu_exact(float x) {
    return 0.5f * x * (1.0f + erff(x * 0.7071067811865476f));
}
__device__ __forceinline__ void split1(float v, bf16& h, bf16& l) {
    h = __float2bfloat16(v);
    l = __float2bfloat16(v - __bfloat162float(h));
}

// ---------------- merged weight split ----------------
struct SJ {
    const float* s[8];
    bf16* h[8];
    bf16* l[8];
    int cum[9];
};
__global__ void __launch_bounds__(256) split_all(SJ j) {
    int blk = blockIdx.x;
    int ti = 0;
#pragma unroll
    for (int i = 0; i < 7; i++) ti += (blk >= j.cum[i + 1]) ? 1 : 0;
    int idx = (blk - j.cum[ti]) * 256 + threadIdx.x;
    float4 v = ((const float4*)j.s[ti])[idx];
    bf16 h0, l0, h1, l1, h2, l2, h3, l3;
    split1(v.x, h0, l0); split1(v.y, h1, l1); split1(v.z, h2, l2); split1(v.w, h3, l3);
    ((bf162*)j.h[ti])[2 * idx]     = bf162(h0, h1);
    ((bf162*)j.h[ti])[2 * idx + 1] = bf162(h2, h3);
    ((bf162*)j.l[ti])[2 * idx]     = bf162(l0, l1);
    ((bf162*)j.l[ti])[2 * idx + 1] = bf162(l2, l3);
}

// ---------------- LayerNorm ----------------
__global__ void __launch_bounds__(256) ln_kernel(const float* __restrict__ x,
                                                 const float* __restrict__ res,
                                                 const float* __restrict__ gam,
                                                 const float* __restrict__ bet,
                                                 float* __restrict__ yf,
                                                 bf16* __restrict__ yh,
                                                 bf16* __restrict__ yl) {
    int row = blockIdx.x;
    int tid = threadIdx.x;
    float4 v = ((const float4*)(x + (size_t)row * Dd))[tid];
    if (res) {
        float4 r = ((const float4*)(res + (size_t)row * Dd))[tid];
        v.x += r.x; v.y += r.y; v.z += r.z; v.w += r.w;
    }
    float s  = v.x + v.y + v.z + v.w;
    float ss = v.x * v.x + v.y * v.y + v.z * v.z + v.w * v.w;
#pragma unroll
    for (int o = 16; o > 0; o >>= 1) {
        s  += __shfl_down_sync(0xffffffffu, s, o);
        ss += __shfl_down_sync(0xffffffffu, ss, o);
    }
    __shared__ float wsum[8], wsq[8];
    __shared__ float smean, srstd;
    int w = tid >> 5, l = tid & 31;
    if (l == 0) { wsum[w] = s; wsq[w] = ss; }
    __syncthreads();
    if (tid == 0) {
        float S = 0.f, SS = 0.f;
#pragma unroll
        for (int i = 0; i < 8; i++) { S += wsum[i]; SS += wsq[i]; }
        float mean = S * (1.0f / Dd);
        float var  = SS * (1.0f / Dd) - mean * mean;
        smean = mean;
        srstd = rsqrtf(var + 1e-5f);
    }
    __syncthreads();
    float mean = smean, rstd = srstd;
    float4 gg = ((const float4*)gam)[tid];
    float4 bb = ((const float4*)bet)[tid];
    float4 o;
    o.x = (v.x - mean) * rstd * gg.x + bb.x;
    o.y = (v.y - mean) * rstd * gg.y + bb.y;
    o.z = (v.z - mean) * rstd * gg.z + bb.z;
    o.w = (v.w - mean) * rstd * gg.w + bb.w;
    if (yf) ((float4*)(yf + (size_t)row * Dd))[tid] = o;
    if (yh) {
        bf16 h0, l0, h1, l1, h2, l2, h3, l3;
        split1(o.x, h0, l0); split1(o.y, h1, l1); split1(o.z, h2, l2); split1(o.w, h3, l3);
        bf162* hp = (bf162*)(yh + (size_t)row * Dd);
        bf162* lp = (bf162*)(yl + (size_t)row * Dd);
        hp[2 * tid] = bf162(h0, h1); hp[2 * tid + 1] = bf162(h2, h3);
        lp[2 * tid] = bf162(l0, l1); lp[2 * tid + 1] = bf162(l2, l3);
    }
}

__global__ void __launch_bounds__(256) bcast_slots(const float* __restrict__ si,
                                                   float* __restrict__ slots) {
    int idx = blockIdx.x * 256 + threadIdx.x;
    slots[idx] = si[idx & (KS * Dd - 1)];
}

// ---------------- softmax over SLOT axis ----------------
__global__ void __launch_bounds__(256) softmax_slots(const float* __restrict__ attn,
                                                     bf16* __restrict__ awh,
                                                     bf16* __restrict__ awl) {
    int idx = blockIdx.x * 256 + threadIdx.x;
    int b = idx >> 12;
    int n = idx & (Nn - 1);
    const float* p = attn + (size_t)b * KS * Nn + n;
    float m = -1e30f;
#pragma unroll 8
    for (int k = 0; k < KS; k++) m = fmaxf(m, p[(size_t)k * Nn]);
    float s = 0.f;
#pragma unroll 8
    for (int k = 0; k < KS; k++) s += expf(p[(size_t)k * Nn] - m);
    float inv = 1.0f / s;
    size_t base = (size_t)b * KS * Nn + n;
#pragma unroll 8
    for (int k = 0; k < KS; k++) {
        float e = expf(p[(size_t)k * Nn] - m) * inv;
        bf16 h, l;
        split1(e, h, l);
        awh[base + (size_t)k * Nn] = h;
        awl[base + (size_t)k * Nn] = l;
    }
}

// ---------------- MHA inner ----------------
__global__ void __launch_bounds__(256) mha_scores(const float* __restrict__ qkv,
                                                  float* __restrict__ P) {
    int bh = blockIdx.x;
    int b = bh / Hh, h = bh % Hh;
    const float* base = qkv + (size_t)b * KS * 3 * Dd;
    __shared__ float sk[KS][DHh + 1];
    int tid = threadIdx.x;
    for (int i = tid; i < KS * DHh; i += 256) {
        int kj = i >> 7, dd = i & 127;
        sk[kj][dd] = base[(size_t)kj * 3 * Dd + Dd + h * DHh + dd];
    }
    __syncthreads();
    int w = tid >> 5, lane = tid & 31;
    const float rsDH = 0.08838834764831845f;
    for (int r = 0; r < 8; r++) {
        int qi = w * 8 + r;
        const float* qrow = base + (size_t)qi * 3 * Dd + h * DHh;
        float s0 = 0.f, s1 = 0.f;
#pragma unroll 4
        for (int dd = 0; dd < DHh; dd++) {
            float qd = qrow[dd];
            s0 = fmaf(qd, sk[lane][dd], s0);
            s1 = fmaf(qd, sk[lane + 32][dd], s1);
        }
        s0 *= rsDH; s1 *= rsDH;
        float mx = fmaxf(s0, s1);
#pragma unroll
        for (int o = 16; o > 0; o >>= 1) mx = fmaxf(mx, __shfl_xor_sync(0xffffffffu, mx, o));
        float e0 = expf(s0 - mx), e1 = expf(s1 - mx);
        float sum = e0 + e1;
#pragma unroll
        for (int o = 16; o > 0; o >>= 1) sum += __shfl_xor_sync(0xffffffffu, sum, o);
        float inv = 1.0f / sum;
        P[(size_t)bh * 4096 + qi * 64 + lane]      = e0 * inv;
        P[(size_t)bh * 4096 + qi * 64 + lane + 32] = e1 * inv;
    }
}

__global__ void __launch_bounds__(256) mha_av(const float* __restrict__ qkv,
                                              const float* __restrict__ P,
                                              bf16* __restrict__ sah,
                                              bf16* __restrict__ sal) {
    int bh = blockIdx.x;
    int b = bh / Hh, h = bh % Hh;
    const float* vbase = qkv + (size_t)b * KS * 3 * Dd + 2 * Dd + h * DHh;
    __shared__ float sv[KS][DHh];
    __shared__ float sp[KS][KS];
    int tid = threadIdx.x;
    for (int i = tid; i < KS * DHh; i += 256) {
        int kj = i >> 7, dd = i & 127;
        sv[kj][dd] = vbase[(size_t)kj * 3 * Dd + dd];
    }
    for (int i = tid; i < KS * KS; i += 256)
        sp[i >> 6][i & 63] = P[(size_t)bh * 4096 + i];
    __syncthreads();
    int d = tid & 127;
    int half = tid >> 7;
    for (int j0 = 0; j0 < 32; j0 += 4) {
        int qi = half * 32 + j0;
        float a0 = 0.f, a1 = 0.f, a2 = 0.f, a3 = 0.f;
#pragma unroll 8
        for (int kj = 0; kj < KS; kj++) {
            float vv = sv[kj][d];
            a0 = fmaf(sp[qi][kj],     vv, a0);
            a1 = fmaf(sp[qi + 1][kj], vv, a1);
            a2 = fmaf(sp[qi + 2][kj], vv, a2);
            a3 = fmaf(sp[qi + 3][kj], vv, a3);
        }
        size_t o = (size_t)b * KS * Dd + (size_t)qi * Dd + h * DHh + d;
        bf16 h0, l0;
        split1(a0, h0, l0); sah[o] = h0;          sal[o] = l0;
        split1(a1, h0, l0); sah[o + Dd] = h0;     sal[o + Dd] = l0;
        split1(a2, h0, l0); sah[o + 2 * Dd] = h0; sal[o + 2 * Dd] = l0;
        split1(a3, h0, l0); sah[o + 3 * Dd] = h0; sal[o + 3 * Dd] = l0;
    }
}

// ================= split-bf16 GEMM v3: BK=64, 2-stage, 4 warps, 1 barrier/tile =================
// BM=64. BN in {64,128}. 128 threads, warp grid 2x2, warp tile 32 x (BN/2).
// TB=true:  C = alpha*A@B^T, B [n][k] k-contig (NT)
// TB=false: C = alpha*A@B,   B [k][n] n-contig (NN, ldmatrix.trans)

__device__ __forceinline__ void mma_bf16(float* d, const uint32_t* a, uint32_t b0, uint32_t b1) {
    asm volatile(
        "mma.sync.aligned.m16n8k16.row.col.f32.bf16.bf16.f32 "
        "{%0,%1,%2,%3}, {%4,%5,%6,%7}, {%8,%9}, {%0,%1,%2,%3};\n"
        : "+f"(d[0]), "+f"(d[1]), "+f"(d[2]), "+f"(d[3])
        : "r"(a[0]), "r"(a[1]), "r"(a[2]), "r"(a[3]), "r"(b0), "r"(b1));
}
__device__ __forceinline__ void cp16(bf16* s, const bf16* g) {
    uint32_t sa = (uint32_t)__cvta_generic_to_shared(s);
    asm volatile("cp.async.cg.shared.global [%0], [%1], 16;\n" :: "r"(sa), "l"(g));
}
#define LDSM4(r0, r1, r2, r3, a) \
    asm volatile("ldmatrix.sync.aligned.m8n8.x4.shared.b16 {%0,%1,%2,%3}, [%4];\n" \
                 : "=r"(r0), "=r"(r1), "=r"(r2), "=r"(r3) : "r"(a))
#define LDSM4T(r0, r1, r2, r3, a) \
    asm volatile("ldmatrix.sync.aligned.m8n8.x4.trans.shared.b16 {%0,%1,%2,%3}, [%4];\n" \
                 : "=r"(r0), "=r"(r1), "=r"(r2), "=r"(r3) : "r"(a))

template <bool TB, int BN>
__global__ void __launch_bounds__(128) gemm3(
    const bf16* __restrict__ Ah, const bf16* __restrict__ Al,
    const bf16* __restrict__ Bh, const bf16* __restrict__ Bl,
    int Kd, int ldb, long long sA, long long sB, float alpha,
    float* __restrict__ Cf, int ldc, long long sC,
    bf16* __restrict__ Ch, bf16* __restrict__ Cl, int ldch, long long sCh,
    const float* __restrict__ bias,
    const float* __restrict__ add, int ldadd, long long sAdd, int act) {
    constexpr int NPW = BN / 2;          // warp n extent
    constexpr int PP  = NPW / 16;        // ldsm passes along n
    constexpr int NS  = NPW / 8;         // n subtiles
    constexpr int BOF = 9216;            // A region: 64 rows hi + 64 lo, stride 72
    constexpr int BROW = TB ? 72 : (BN + 8);
    constexpr int BSZH = TB ? BN * 72 : 64 * (BN + 8);
    constexpr int STG = BOF + 2 * BSZH;
    extern __shared__ __align__(16) bf16 sm[];

    int bz = blockIdx.z;
    Ah += bz * sA; Al += bz * sA;
    Bh += bz * sB; Bl += bz * sB;
    if (Cf) Cf += bz * sC;
    if (Ch) { Ch += bz * sCh; Cl += bz * sCh; }
    if (add) add += bz * sAdd;

    int bm = blockIdx.y * 64;
    int bn = blockIdx.x * BN;
    int tid = threadIdx.x, lane = tid & 31, wid = tid >> 5;
    int wm = (wid >> 1) * 32;
    int wn = (wid & 1) * NPW;
    int r = lane >> 2, cc = lane & 3;
    int arow = lane & 15, ahalf = lane >> 4;

    float acc[2][NS][4] = {};

    auto load_tile = [&](int st, int k0) {
        bf16* s = sm + st * STG;
#pragma unroll
        for (int c = tid; c < 512; c += 128) {
            int row = c >> 3, kq = c & 7;
            cp16(s + row * 72 + kq * 8,        Ah + (size_t)(bm + row) * Kd + k0 + kq * 8);
            cp16(s + 4608 + row * 72 + kq * 8, Al + (size_t)(bm + row) * Kd + k0 + kq * 8);
        }
        if (TB) {
#pragma unroll
            for (int c = tid; c < BN * 8; c += 128) {
                int row = c >> 3, kq = c & 7;
                cp16(s + BOF + row * 72 + kq * 8,        Bh + (size_t)(bn + row) * ldb + k0 + kq * 8);
                cp16(s + BOF + BSZH + row * 72 + kq * 8, Bl + (size_t)(bn + row) * ldb + k0 + kq * 8);
            }
        } else {
            constexpr int CH = BN / 8;
#pragma unroll
            for (int c = tid; c < 64 * CH; c += 128) {
                int row = c / CH, ch = c % CH;
                cp16(s + BOF + row * BROW + ch * 8,        Bh + (size_t)(k0 + row) * ldb + bn + ch * 8);
                cp16(s + BOF + BSZH + row * BROW + ch * 8, Bl + (size_t)(k0 + row) * ldb + bn + ch * 8);
            }
        }
        asm volatile("cp.async.commit_group;\n");
    };

    int T = Kd / 64;
    load_tile(0, 0);
    uint32_t smem_base = (uint32_t)__cvta_generic_to_shared(sm);

    for (int t = 0; t < T; t++) {
        asm volatile("cp.async.wait_group 0;\n");
        __syncthreads();
        if (t + 1 < T) load_tile((t + 1) & 1, (t + 1) * 64);
        uint32_t base = smem_base + (t & 1) * STG * 2;
#pragma unroll
        for (int s = 0; s < 4; s++) {
            uint32_t ah[2][4], al[2][4], bh[NS][2], bl[NS][2];
#pragma unroll
            for (int ms = 0; ms < 2; ms++) {
                uint32_t ad = base + ((wm + ms * 16 + arow) * 72 + s * 16 + ahalf * 8) * 2;
                LDSM4(ah[ms][0], ah[ms][1], ah[ms][2], ah[ms][3], ad);
                LDSM4(al[ms][0], al[ms][1], al[ms][2], al[ms][3], ad + 9216);
            }
            if (TB) {
#pragma unroll
                for (int pp = 0; pp < PP; pp++) {
                    uint32_t bd = base + (BOF + (wn + pp * 16 + arow) * 72 + s * 16 + ahalf * 8) * 2;
                    uint32_t r0, r1, r2, r3;
                    LDSM4(r0, r1, r2, r3, bd);
                    bh[2 * pp][0] = r0; bh[2 * pp + 1][0] = r1;
                    bh[2 * pp][1] = r2; bh[2 * pp + 1][1] = r3;
                    LDSM4(r0, r1, r2, r3, bd + BSZH * 2);
                    bl[2 * pp][0] = r0; bl[2 * pp + 1][0] = r1;
                    bl[2 * pp][1] = r2; bl[2 * pp + 1][1] = r3;
                }
            } else {
#pragma unroll
                for (int pp = 0; pp < PP; pp++) {
                    uint32_t bd = base + (BOF + (s * 16 + arow) * BROW + wn + pp * 16 + ahalf * 8) * 2;
                    uint32_t r0, r1, r2, r3;
                    LDSM4T(r0, r1, r2, r3, bd);
                    bh[2 * pp][0] = r0; bh[2 * pp][1] = r1;
                    bh[2 * pp + 1][0] = r2; bh[2 * pp + 1][1] = r3;
                    LDSM4T(r0, r1, r2, r3, bd + BSZH * 2);
                    bl[2 * pp][0] = r0; bl[2 * pp][1] = r1;
                    bl[2 * pp + 1][0] = r2; bl[2 * pp + 1][1] = r3;
                }
            }
            // term-major: consecutive MMAs hit different accumulators
#pragma unroll
            for (int ns = 0; ns < NS; ns++)
#pragma unroll
                for (int ms = 0; ms < 2; ms++)
                    mma_bf16(acc[ms][ns], ah[ms], bh[ns][0], bh[ns][1]);
#pragma unroll
            for (int ns = 0; ns < NS; ns++)
#pragma unroll
                for (int ms = 0; ms < 2; ms++)
                    mma_bf16(acc[ms][ns], ah[ms], bl[ns][0], bl[ns][1]);
#pragma unroll
            for (int ns = 0; ns < NS; ns++)
#pragma unroll
                for (int ms = 0; ms < 2; ms++)
                    mma_bf16(acc[ms][ns], al[ms], bh[ns][0], bh[ns][1]);
        }
        __syncthreads();
    }

    // epilogue
#pragma unroll
    for (int ms = 0; ms < 2; ms++) {
        int i0 = bm + wm + ms * 16 + r;
#pragma unroll
        for (int ns = 0; ns < NS; ns++) {
            int j = bn + wn + ns * 8 + 2 * cc;
            float v00 = acc[ms][ns][0] * alpha, v01 = acc[ms][ns][1] * alpha;
            float v10 = acc[ms][ns][2] * alpha, v11 = acc[ms][ns][3] * alpha;
            if (bias) {
                float bj0 = bias[j], bj1 = bias[j + 1];
                v00 += bj0; v01 += bj1; v10 += bj0; v11 += bj1;
            }
            if (act == 1) {
                v00 = gelu_exact(v00); v01 = gelu_exact(v01);
                v10 = gelu_exact(v10); v11 = gelu_exact(v11);
            }
            if (add) {
                v00 += add[(size_t)i0 * ldadd + j];
                v01 += add[(size_t)i0 * ldadd + j + 1];
                v10 += add[(size_t)(i0 + 8) * ldadd + j];
                v11 += add[(size_t)(i0 + 8) * ldadd + j + 1];
            }
            if (Cf) {
                float2 a2; a2.x = v00; a2.y = v01;
                float2 b2; b2.x = v10; b2.y = v11;
                *(float2*)(Cf + (size_t)i0 * ldc + j) = a2;
                *(float2*)(Cf + (size_t)(i0 + 8) * ldc + j) = b2;
            }
            if (Ch) {
                bf16 h00, l00, h01, l01, h10, l10, h11, l11;
                split1(v00, h00, l00); split1(v01, h01, l01);
                split1(v10, h10, l10); split1(v11, h11, l11);
                *(bf162*)(Ch + (size_t)i0 * ldch + j) = bf162(h00, h01);
                *(bf162*)(Cl + (size_t)i0 * ldch + j) = bf162(l00, l01);
                *(bf162*)(Ch + (size_t)(i0 + 8) * ldch + j) = bf162(h10, h11);
                *(bf162*)(Cl + (size_t)(i0 + 8) * ldch + j) = bf162(l10, l11);
            }
        }
    }
}

// ---------------- launcher ----------------
#define SYM(p, s) cudaGetSymbolAddress((void**)&p, s)

extern "C" void kernel_launch(void* const* d_in, const int* in_sizes, int n_in,
                              void* d_out, int out_size) {
    const float* vis       = (const float*)d_in[0];
    const float* slot_init = (const float*)d_in[1];
    const float* ln_vis_g  = (const float*)d_in[2];
    const float* ln_vis_b  = (const float*)d_in[3];
    const float* ln_sl_g   = (const float*)d_in[4];
    const float* ln_sl_b   = (const float*)d_in[5];
    const float* Wq        = (const float*)d_in[6];
    const float* Wk        = (const float*)d_in[7];
    const float* Wv        = (const float*)d_in[8];
    const float* Wo        = (const float*)d_in[9];
    const float* mha_in_w  = (const float*)d_in[10];
    const float* mha_in_b  = (const float*)d_in[11];
    const float* mha_out_w = (const float*)d_in[12];
    const float* mha_out_b = (const float*)d_in[13];
    const float* ln_sa_g   = (const float*)d_in[14];
    const float* ln_sa_b   = (const float*)d_in[15];
    const float* ln_ffn_g  = (const float*)d_in[16];
    const float* ln_ffn_b  = (const float*)d_in[17];
    const float* W1        = (const float*)d_in[18];
    const float* b1        = (const float*)d_in[19];
    const float* W2        = (const float*)d_in[20];
    const float* b2        = (const float*)d_in[21];

    bf16 *vnh, *vnl, *Wkh, *Wkl, *Wqh, *Wql, *Wvh, *Wvl, *Woh, *Wol;
    bf16 *Wqkh, *Wqkl, *Wvoh, *Wvol, *miwh, *miwl, *mowh, *mowl;
    bf16 *W1h, *W1l, *W2h, *W2l, *snh, *snl, *qh, *ql, *awh, *awl;
    bf16 *u1h, *u1l, *slbh, *slbl, *sah, *sal, *hh, *hl, *tbh, *tbl;
    float *slots, *attn, *qkv, *P, *tmp;
    SYM(vnh, g_vnh); SYM(vnl, g_vnl);
    SYM(Wkh, g_Wkh); SYM(Wkl, g_Wkl); SYM(Wqh, g_Wqh); SYM(Wql, g_Wql);
    SYM(Wvh, g_Wvh); SYM(Wvl, g_Wvl); SYM(Woh, g_Woh); SYM(Wol, g_Wol);
    SYM(Wqkh, g_Wqkh); SYM(Wqkl, g_Wqkl); SYM(Wvoh, g_Wvoh); SYM(Wvol, g_Wvol);
    SYM(miwh, g_miwh); SYM(miwl, g_miwl); SYM(mowh, g_mowh); SYM(mowl, g_mowl);
    SYM(W1h, g_W1h); SYM(W1l, g_W1l); SYM(W2h, g_W2h); SYM(W2l, g_W2l);
    SYM(snh, g_snh); SYM(snl, g_snl); SYM(qh, g_qh); SYM(ql, g_ql);
    SYM(awh, g_awh); SYM(awl, g_awl); SYM(u1h, g_u1h); SYM(u1l, g_u1l);
    SYM(slbh, g_slbh); SYM(slbl, g_slbl); SYM(sah, g_sah); SYM(sal, g_sal);
    SYM(hh, g_hh); SYM(hl, g_hl); SYM(tbh, g_tbh); SYM(tbl, g_tbl);
    SYM(slots, g_slots); SYM(attn, g_attn); SYM(qkv, g_qkv); SYM(P, g_P); SYM(tmp, g_tmp);

    float* out = (float*)d_out;

    // smem: STG*2 stages*2 bytes
    const int SM_NT128 = (9216 + 2 * 128 * 72) * 2 * 2;      // 110592
    const int SM_NT64  = (9216 + 2 * 64 * 72) * 2 * 2;       // 73728
    const int SM_NN128 = (9216 + 2 * 64 * 136) * 2 * 2;      // 106496
    const int SM_NN64  = (9216 + 2 * 64 * 72) * 2 * 2;       // 73728
    cudaFuncSetAttribute(gemm3<true, 128>,  cudaFuncAttributeMaxDynamicSharedMemorySize, SM_NT128);
    cudaFuncSetAttribute(gemm3<true, 64>,   cudaFuncAttributeMaxDynamicSharedMemorySize, SM_NT64);
    cudaFuncSetAttribute(gemm3<false, 128>, cudaFuncAttributeMaxDynamicSharedMemorySize, SM_NN128);
    cudaFuncSetAttribute(gemm3<false, 64>,  cudaFuncAttributeMaxDynamicSharedMemorySize, SM_NN64);

    // ---- merged weight split ----
    {
        SJ j;
        j.s[0] = Wq;  j.h[0] = Wqh;  j.l[0] = Wql;
        j.s[1] = Wk;  j.h[1] = Wkh;  j.l[1] = Wkl;
        j.s[2] = Wv;  j.h[2] = Wvh;  j.l[2] = Wvl;
        j.s[3] = Wo;  j.h[3] = Woh;  j.l[3] = Wol;
        j.s[4] = mha_out_w; j.h[4] = mowh; j.l[4] = mowl;
        j.s[5] = mha_in_w;  j.h[5] = miwh; j.l[5] = miwl;
        j.s[6] = W1;  j.h[6] = W1h;  j.l[6] = W1l;
        j.s[7] = W2;  j.h[7] = W2h;  j.l[7] = W2l;
        int blocks[8] = {1024, 1024, 1024, 1024, 1024, 3072, 2048, 2048};
        j.cum[0] = 0;
        for (int i = 0; i < 8; i++) j.cum[i + 1] = j.cum[i] + blocks[i];
        split_all<<<j.cum[8], 256>>>(j);
    }

    // vn = LN(visual_tokens) -> split bf16
    ln_kernel<<<Bb * Nn, 256>>>(vis, nullptr, ln_vis_g, ln_vis_b, nullptr, vnh, vnl);

    // Wqk = Wq @ Wk^T (NT); Wvo = Wv @ Wo (NN)
    gemm3<true, 64><<<dim3(16, 16, 1), 128, SM_NT64>>>(Wqh, Wql, Wkh, Wkl, Dd, Dd, 0, 0, 1.0f,
        nullptr, 0, 0, Wqkh, Wqkl, Dd, 0, nullptr, nullptr, 0, 0, 0);
    gemm3<false, 64><<<dim3(16, 16, 1), 128, SM_NN64>>>(Wvh, Wvl, Woh, Wol, Dd, Dd, 0, 0, 1.0f,
        nullptr, 0, 0, Wvoh, Wvol, Dd, 0, nullptr, nullptr, 0, 0, 0);

    bcast_slots<<<(Bb * KS * Dd) / 256, 256>>>(slot_init, slots);

    const int Mfull = Bb * KS;  // 1024
    for (int it = 0; it < 2; it++) {
        ln_kernel<<<Mfull, 256>>>(slots, nullptr, ln_sl_g, ln_sl_b, nullptr, snh, snl);
        // q = sn @ Wqk  (NN)
        gemm3<false, 64><<<dim3(16, 16, 1), 128, SM_NN64>>>(snh, snl, Wqkh, Wqkl, Dd, Dd, 0, 0, 1.0f,
            nullptr, 0, 0, qh, ql, Dd, 0, nullptr, nullptr, 0, 0, 0);
        // attn[b] = (1/32) q[b] @ vn[b]^T  (NT, N=4096)
        gemm3<true, 128><<<dim3(32, 1, Bb), 128, SM_NT128>>>(qh, ql, vnh, vnl, Dd, Dd,
            (long long)KS * Dd, (long long)Nn * Dd, 0.03125f,
            attn, Nn, (long long)KS * Nn, nullptr, nullptr, 0, 0,
            nullptr, nullptr, 0, 0, 0);
        softmax_slots<<<(Bb * Nn) / 256, 256>>>(attn, awh, awl);
        // u1[b] = aw[b] @ vn[b]  (NN, K=4096)
        gemm3<false, 64><<<dim3(16, 1, Bb), 128, SM_NN64>>>(awh, awl, vnh, vnl, Nn, Dd,
            (long long)KS * Nn, (long long)Nn * Dd, 1.0f,
            nullptr, 0, 0, u1h, u1l, Dd, (long long)KS * Dd,
            nullptr, nullptr, 0, 0, 0);
        // slots = slots + u1 @ Wvo  (NN)
        gemm3<false, 64><<<dim3(16, 16, 1), 128, SM_NN64>>>(u1h, u1l, Wvoh, Wvol, Dd, Dd, 0, 0, 1.0f,
            slots, Dd, 0, slbh, slbl, Dd, 0, nullptr, slots, Dd, 0, 0);
        // qkv = slots @ mha_in_w^T + b  (NT, N=3072)
        gemm3<true, 128><<<dim3(24, 16, 1), 128, SM_NT128>>>(slbh, slbl, miwh, miwl, Dd, Dd, 0, 0, 1.0f,
            qkv, 3 * Dd, 0, nullptr, nullptr, 0, 0, mha_in_b, nullptr, 0, 0, 0);
        mha_scores<<<Bb * Hh, 256>>>(qkv, P);
        mha_av<<<Bb * Hh, 256>>>(qkv, P, sah, sal);
        // tmp = sa @ mha_out_w^T + b  (NT)
        gemm3<true, 64><<<dim3(16, 16, 1), 128, SM_NT64>>>(sah, sal, mowh, mowl, Dd, Dd, 0, 0, 1.0f,
            tmp, Dd, 0, nullptr, nullptr, 0, 0, mha_out_b, nullptr, 0, 0, 0);
        ln_kernel<<<Mfull, 256>>>(slots, tmp, ln_sa_g, ln_sa_b, slots, nullptr, nullptr);
    }

    ln_kernel<<<Mfull, 256>>>(slots, nullptr, ln_ffn_g, ln_ffn_b, nullptr, hh, hl);
    // tb = gelu(h @ W1 + b1)  (NN, N=2048)
    gemm3<false, 128><<<dim3(16, 16, 1), 128, SM_NN128>>>(hh, hl, W1h, W1l, Dd, 2 * Dd, 0, 0, 1.0f,
        nullptr, 0, 0, tbh, tbl, 2 * Dd, 0, b1, nullptr, 0, 0, 1);
    // out = slots + tb @ W2 + b2  (NN, K=2048)
    gemm3<false, 64><<<dim3(16, 16, 1), 128, SM_NN64>>>(tbh, tbl, W2h, W2l, 2 * Dd, Dd, 0, 0, 1.0f,
        out, Dd, 0, nullptr, nullptr, 0, 0, b2, slots, Dd, 0, 0);
}

// round 9
// speedup vs baseline: 3.4598x; 1.0062x over previous
#include <cuda_runtime.h>
#include <cuda_bf16.h>
#include <cstdint>

#define Bb 16
#define Nn 4096
#define KS 64
#define Dd 1024
#define Hh 8
#define DHh 128

typedef __nv_bfloat16 bf16;
typedef __nv_bfloat162 bf162;

// ---------------- scratch (device globals) ----------------
__device__ __align__(256) bf16 g_vnh[(size_t)Bb * Nn * Dd];
__device__ __align__(256) bf16 g_vnl[(size_t)Bb * Nn * Dd];
__device__ __align__(256) bf16 g_Wkh[Dd * Dd], g_Wkl[Dd * Dd];
__device__ __align__(256) bf16 g_Wqh[Dd * Dd], g_Wql[Dd * Dd];
__device__ __align__(256) bf16 g_Wvh[Dd * Dd], g_Wvl[Dd * Dd];
__device__ __align__(256) bf16 g_Woh[Dd * Dd], g_Wol[Dd * Dd];
__device__ __align__(256) bf16 g_Wqkh[Dd * Dd], g_Wqkl[Dd * Dd];
__device__ __align__(256) bf16 g_Wvoh[Dd * Dd], g_Wvol[Dd * Dd];
__device__ __align__(256) bf16 g_miwh[3 * Dd * Dd], g_miwl[3 * Dd * Dd];
__device__ __align__(256) bf16 g_mowh[Dd * Dd], g_mowl[Dd * Dd];
__device__ __align__(256) bf16 g_W1h[2 * Dd * Dd], g_W1l[2 * Dd * Dd];
__device__ __align__(256) bf16 g_W2h[2 * Dd * Dd], g_W2l[2 * Dd * Dd];
__device__ __align__(256) bf16 g_snh[Bb * KS * Dd], g_snl[Bb * KS * Dd];
__device__ __align__(256) bf16 g_qh[Bb * KS * Dd], g_ql[Bb * KS * Dd];
__device__ __align__(256) bf16 g_awh[(size_t)Bb * KS * Nn], g_awl[(size_t)Bb * KS * Nn];
__device__ __align__(256) bf16 g_u1h[Bb * KS * Dd], g_u1l[Bb * KS * Dd];
__device__ __align__(256) bf16 g_slbh[Bb * KS * Dd], g_slbl[Bb * KS * Dd];
__device__ __align__(256) bf16 g_sah[Bb * KS * Dd], g_sal[Bb * KS * Dd];
__device__ __align__(256) bf16 g_hh[Bb * KS * Dd], g_hl[Bb * KS * Dd];
__device__ __align__(256) bf16 g_tbh[Bb * KS * 2 * Dd], g_tbl[Bb * KS * 2 * Dd];
__device__ __align__(256) float g_slots[Bb * KS * Dd];
__device__ __align__(256) float g_attn[(size_t)Bb * KS * Nn];
__device__ __align__(256) float g_qkv[Bb * KS * 3 * Dd];
__device__ __align__(256) float g_P[Bb * Hh * KS * KS];
__device__ __align__(256) float g_tmp[Bb * KS * Dd];

__device__ __forceinline__ float gelu_exact(float x) {
    return 0.5f * x * (1.0f + erff(x * 0.7071067811865476f));
}
__device__ __forceinline__ void split1(float v, bf16& h, bf16& l) {
    h = __float2bfloat16(v);
    l = __float2bfloat16(v - __bfloat162float(h));
}

// ---------------- merged weight split ----------------
struct SJ {
    const float* s[8];
    bf16* h[8];
    bf16* l[8];
    int cum[9];
};
__global__ void __launch_bounds__(256) split_all(SJ j) {
    int blk = blockIdx.x;
    int ti = 0;
#pragma unroll
    for (int i = 0; i < 7; i++) ti += (blk >= j.cum[i + 1]) ? 1 : 0;
    int idx = (blk - j.cum[ti]) * 256 + threadIdx.x;
    float4 v = ((const float4*)j.s[ti])[idx];
    bf16 h0, l0, h1, l1, h2, l2, h3, l3;
    split1(v.x, h0, l0); split1(v.y, h1, l1); split1(v.z, h2, l2); split1(v.w, h3, l3);
    ((bf162*)j.h[ti])[2 * idx]     = bf162(h0, h1);
    ((bf162*)j.h[ti])[2 * idx + 1] = bf162(h2, h3);
    ((bf162*)j.l[ti])[2 * idx]     = bf162(l0, l1);
    ((bf162*)j.l[ti])[2 * idx + 1] = bf162(l2, l3);
}

// ---------------- LayerNorm ----------------
__global__ void __launch_bounds__(256) ln_kernel(const float* __restrict__ x,
                                                 const float* __restrict__ res,
                                                 const float* __restrict__ gam,
                                                 const float* __restrict__ bet,
                                                 float* __restrict__ yf,
                                                 bf16* __restrict__ yh,
                                                 bf16* __restrict__ yl) {
    int row = blockIdx.x;
    int tid = threadIdx.x;
    float4 v = ((const float4*)(x + (size_t)row * Dd))[tid];
    if (res) {
        float4 r = ((const float4*)(res + (size_t)row * Dd))[tid];
        v.x += r.x; v.y += r.y; v.z += r.z; v.w += r.w;
    }
    float s  = v.x + v.y + v.z + v.w;
    float ss = v.x * v.x + v.y * v.y + v.z * v.z + v.w * v.w;
#pragma unroll
    for (int o = 16; o > 0; o >>= 1) {
        s  += __shfl_down_sync(0xffffffffu, s, o);
        ss += __shfl_down_sync(0xffffffffu, ss, o);
    }
    __shared__ float wsum[8], wsq[8];
    __shared__ float smean, srstd;
    int w = tid >> 5, l = tid & 31;
    if (l == 0) { wsum[w] = s; wsq[w] = ss; }
    __syncthreads();
    if (tid == 0) {
        float S = 0.f, SS = 0.f;
#pragma unroll
        for (int i = 0; i < 8; i++) { S += wsum[i]; SS += wsq[i]; }
        float mean = S * (1.0f / Dd);
        float var  = SS * (1.0f / Dd) - mean * mean;
        smean = mean;
        srstd = rsqrtf(var + 1e-5f);
    }
    __syncthreads();
    float mean = smean, rstd = srstd;
    float4 gg = ((const float4*)gam)[tid];
    float4 bb = ((const float4*)bet)[tid];
    float4 o;
    o.x = (v.x - mean) * rstd * gg.x + bb.x;
    o.y = (v.y - mean) * rstd * gg.y + bb.y;
    o.z = (v.z - mean) * rstd * gg.z + bb.z;
    o.w = (v.w - mean) * rstd * gg.w + bb.w;
    if (yf) ((float4*)(yf + (size_t)row * Dd))[tid] = o;
    if (yh) {
        bf16 h0, l0, h1, l1, h2, l2, h3, l3;
        split1(o.x, h0, l0); split1(o.y, h1, l1); split1(o.z, h2, l2); split1(o.w, h3, l3);
        bf162* hp = (bf162*)(yh + (size_t)row * Dd);
        bf162* lp = (bf162*)(yl + (size_t)row * Dd);
        hp[2 * tid] = bf162(h0, h1); hp[2 * tid + 1] = bf162(h2, h3);
        lp[2 * tid] = bf162(l0, l1); lp[2 * tid + 1] = bf162(l2, l3);
    }
}

__global__ void __launch_bounds__(256) bcast_slots(const float* __restrict__ si,
                                                   float* __restrict__ slots) {
    int idx = blockIdx.x * 256 + threadIdx.x;
    slots[idx] = si[idx & (KS * Dd - 1)];
}

// ---------------- softmax over SLOT axis ----------------
__global__ void __launch_bounds__(256) softmax_slots(const float* __restrict__ attn,
                                                     bf16* __restrict__ awh,
                                                     bf16* __restrict__ awl) {
    int idx = blockIdx.x * 256 + threadIdx.x;
    int b = idx >> 12;
    int n = idx & (Nn - 1);
    const float* p = attn + (size_t)b * KS * Nn + n;
    float m = -1e30f;
#pragma unroll 8
    for (int k = 0; k < KS; k++) m = fmaxf(m, p[(size_t)k * Nn]);
    float s = 0.f;
#pragma unroll 8
    for (int k = 0; k < KS; k++) s += expf(p[(size_t)k * Nn] - m);
    float inv = 1.0f / s;
    size_t base = (size_t)b * KS * Nn + n;
#pragma unroll 8
    for (int k = 0; k < KS; k++) {
        float e = expf(p[(size_t)k * Nn] - m) * inv;
        bf16 h, l;
        split1(e, h, l);
        awh[base + (size_t)k * Nn] = h;
        awl[base + (size_t)k * Nn] = l;
    }
}

// ---------------- MHA inner ----------------
__global__ void __launch_bounds__(256) mha_scores(const float* __restrict__ qkv,
                                                  float* __restrict__ P) {
    int bh = blockIdx.x;
    int b = bh / Hh, h = bh % Hh;
    const float* base = qkv + (size_t)b * KS * 3 * Dd;
    __shared__ float sk[KS][DHh + 1];
    int tid = threadIdx.x;
    for (int i = tid; i < KS * DHh; i += 256) {
        int kj = i >> 7, dd = i & 127;
        sk[kj][dd] = base[(size_t)kj * 3 * Dd + Dd + h * DHh + dd];
    }
    __syncthreads();
    int w = tid >> 5, lane = tid & 31;
    const float rsDH = 0.08838834764831845f;
    for (int r = 0; r < 8; r++) {
        int qi = w * 8 + r;
        const float* qrow = base + (size_t)qi * 3 * Dd + h * DHh;
        float s0 = 0.f, s1 = 0.f;
#pragma unroll 4
        for (int dd = 0; dd < DHh; dd++) {
            float qd = qrow[dd];
            s0 = fmaf(qd, sk[lane][dd], s0);
            s1 = fmaf(qd, sk[lane + 32][dd], s1);
        }
        s0 *= rsDH; s1 *= rsDH;
        float mx = fmaxf(s0, s1);
#pragma unroll
        for (int o = 16; o > 0; o >>= 1) mx = fmaxf(mx, __shfl_xor_sync(0xffffffffu, mx, o));
        float e0 = expf(s0 - mx), e1 = expf(s1 - mx);
        float sum = e0 + e1;
#pragma unroll
        for (int o = 16; o > 0; o >>= 1) sum += __shfl_xor_sync(0xffffffffu, sum, o);
        float inv = 1.0f / sum;
        P[(size_t)bh * 4096 + qi * 64 + lane]      = e0 * inv;
        P[(size_t)bh * 4096 + qi * 64 + lane + 32] = e1 * inv;
    }
}

__global__ void __launch_bounds__(256) mha_av(const float* __restrict__ qkv,
                                              const float* __restrict__ P,
                                              bf16* __restrict__ sah,
                                              bf16* __restrict__ sal) {
    int bh = blockIdx.x;
    int b = bh / Hh, h = bh % Hh;
    const float* vbase = qkv + (size_t)b * KS * 3 * Dd + 2 * Dd + h * DHh;
    __shared__ float sv[KS][DHh];
    __shared__ float sp[KS][KS];
    int tid = threadIdx.x;
    for (int i = tid; i < KS * DHh; i += 256) {
        int kj = i >> 7, dd = i & 127;
        sv[kj][dd] = vbase[(size_t)kj * 3 * Dd + dd];
    }
    for (int i = tid; i < KS * KS; i += 256)
        sp[i >> 6][i & 63] = P[(size_t)bh * 4096 + i];
    __syncthreads();
    int d = tid & 127;
    int half = tid >> 7;
    for (int j0 = 0; j0 < 32; j0 += 4) {
        int qi = half * 32 + j0;
        float a0 = 0.f, a1 = 0.f, a2 = 0.f, a3 = 0.f;
#pragma unroll 8
        for (int kj = 0; kj < KS; kj++) {
            float vv = sv[kj][d];
            a0 = fmaf(sp[qi][kj],     vv, a0);
            a1 = fmaf(sp[qi + 1][kj], vv, a1);
            a2 = fmaf(sp[qi + 2][kj], vv, a2);
            a3 = fmaf(sp[qi + 3][kj], vv, a3);
        }
        size_t o = (size_t)b * KS * Dd + (size_t)qi * Dd + h * DHh + d;
        bf16 h0, l0;
        split1(a0, h0, l0); sah[o] = h0;          sal[o] = l0;
        split1(a1, h0, l0); sah[o + Dd] = h0;     sal[o + Dd] = l0;
        split1(a2, h0, l0); sah[o + 2 * Dd] = h0; sal[o + 2 * Dd] = l0;
        split1(a3, h0, l0); sah[o + 3 * Dd] = h0; sal[o + 3 * Dd] = l0;
    }
}

// ================= split-bf16 GEMM v4: fragment-pipelined, templated tiles =================
// gemmx<TB, BM, BN>: BM in {64,128}, BN in {64,128}. THREADS = 2*BM.
// Warp grid: (BM/32) x 2. Warp tile: 32 x (BN/2). BK=64, 2 smem stages, 1 barrier pair/tile.
// Fragment double-buffering: LDSM for step s+1 overlaps MMA of step s.

__device__ __forceinline__ void mma_bf16(float* d, const uint32_t* a, uint32_t b0, uint32_t b1) {
    asm volatile(
        "mma.sync.aligned.m16n8k16.row.col.f32.bf16.bf16.f32 "
        "{%0,%1,%2,%3}, {%4,%5,%6,%7}, {%8,%9}, {%0,%1,%2,%3};\n"
        : "+f"(d[0]), "+f"(d[1]), "+f"(d[2]), "+f"(d[3])
        : "r"(a[0]), "r"(a[1]), "r"(a[2]), "r"(a[3]), "r"(b0), "r"(b1));
}
__device__ __forceinline__ void cp16(bf16* s, const bf16* g) {
    uint32_t sa = (uint32_t)__cvta_generic_to_shared(s);
    asm volatile("cp.async.cg.shared.global [%0], [%1], 16;\n" :: "r"(sa), "l"(g));
}
#define LDSM4(r0, r1, r2, r3, a) \
    asm volatile("ldmatrix.sync.aligned.m8n8.x4.shared.b16 {%0,%1,%2,%3}, [%4];\n" \
                 : "=r"(r0), "=r"(r1), "=r"(r2), "=r"(r3) : "r"(a))
#define LDSM4T(r0, r1, r2, r3, a) \
    asm volatile("ldmatrix.sync.aligned.m8n8.x4.trans.shared.b16 {%0,%1,%2,%3}, [%4];\n" \
                 : "=r"(r0), "=r"(r1), "=r"(r2), "=r"(r3) : "r"(a))

template <bool TB, int BM, int BN>
__global__ void __launch_bounds__(BM * 2) gemmx(
    const bf16* __restrict__ Ah, const bf16* __restrict__ Al,
    const bf16* __restrict__ Bh, const bf16* __restrict__ Bl,
    int Kd, int ldb, long long sA, long long sB, float alpha,
    float* __restrict__ Cf, int ldc, long long sC,
    bf16* __restrict__ Ch, bf16* __restrict__ Cl, int ldch, long long sCh,
    const float* __restrict__ bias,
    const float* __restrict__ add, int ldadd, long long sAdd, int act) {
    constexpr int THREADS = BM * 2;
    constexpr int NPW = BN / 2;
    constexpr int PP  = NPW / 16;
    constexpr int NS  = NPW / 8;
    constexpr int AOFL = BM * 72;            // A-lo offset (bf16 units)
    constexpr int BOF  = 2 * BM * 72;        // B region offset
    constexpr int BROW = TB ? 72 : (BN + 8);
    constexpr int BSZH = TB ? BN * 72 : 64 * (BN + 8);
    constexpr int STG = BOF + 2 * BSZH;
    extern __shared__ __align__(16) bf16 smg[];

    int bz = blockIdx.z;
    Ah += bz * sA; Al += bz * sA;
    Bh += bz * sB; Bl += bz * sB;
    if (Cf) Cf += bz * sC;
    if (Ch) { Ch += bz * sCh; Cl += bz * sCh; }
    if (add) add += bz * sAdd;

    int bm = blockIdx.y * BM;
    int bn = blockIdx.x * BN;
    int tid = threadIdx.x, lane = tid & 31, wid = tid >> 5;
    int wm = (wid >> 1) * 32;
    int wn = (wid & 1) * NPW;
    int r = lane >> 2, cc = lane & 3;
    int arow = lane & 15, ahalf = lane >> 4;

    float acc[2][NS][4] = {};
    uint32_t ah[2][2][4], al[2][2][4], bh[2][NS][2], bl[2][NS][2];
    uint32_t base = 0;

    auto load_tile = [&](int st, int k0) {
        bf16* s = smg + st * STG;
#pragma unroll
        for (int c = tid; c < BM * 8; c += THREADS) {
            int row = c >> 3, kq = c & 7;
            cp16(s + row * 72 + kq * 8,        Ah + (size_t)(bm + row) * Kd + k0 + kq * 8);
            cp16(s + AOFL + row * 72 + kq * 8, Al + (size_t)(bm + row) * Kd + k0 + kq * 8);
        }
        if (TB) {
#pragma unroll
            for (int c = tid; c < BN * 8; c += THREADS) {
                int row = c >> 3, kq = c & 7;
                cp16(s + BOF + row * 72 + kq * 8,        Bh + (size_t)(bn + row) * ldb + k0 + kq * 8);
                cp16(s + BOF + BSZH + row * 72 + kq * 8, Bl + (size_t)(bn + row) * ldb + k0 + kq * 8);
            }
        } else {
            constexpr int CH = BN / 8;
#pragma unroll
            for (int c = tid; c < 64 * CH; c += THREADS) {
                int row = c / CH, ch = c % CH;
                cp16(s + BOF + row * BROW + ch * 8,        Bh + (size_t)(k0 + row) * ldb + bn + ch * 8);
                cp16(s + BOF + BSZH + row * BROW + ch * 8, Bl + (size_t)(k0 + row) * ldb + bn + ch * 8);
            }
        }
        asm volatile("cp.async.commit_group;\n");
    };

    auto load_frags = [&](int b, int s) {
#pragma unroll
        for (int ms = 0; ms < 2; ms++) {
            uint32_t ad = base + ((wm + ms * 16 + arow) * 72 + s * 16 + ahalf * 8) * 2;
            LDSM4(ah[b][ms][0], ah[b][ms][1], ah[b][ms][2], ah[b][ms][3], ad);
            LDSM4(al[b][ms][0], al[b][ms][1], al[b][ms][2], al[b][ms][3], ad + AOFL * 2);
        }
        if (TB) {
#pragma unroll
            for (int pp = 0; pp < PP; pp++) {
                uint32_t bd = base + (BOF + (wn + pp * 16 + arow) * 72 + s * 16 + ahalf * 8) * 2;
                uint32_t r0, r1, r2, r3;
                LDSM4(r0, r1, r2, r3, bd);
                bh[b][2 * pp][0] = r0; bh[b][2 * pp + 1][0] = r1;
                bh[b][2 * pp][1] = r2; bh[b][2 * pp + 1][1] = r3;
                LDSM4(r0, r1, r2, r3, bd + BSZH * 2);
                bl[b][2 * pp][0] = r0; bl[b][2 * pp + 1][0] = r1;
                bl[b][2 * pp][1] = r2; bl[b][2 * pp + 1][1] = r3;
            }
        } else {
#pragma unroll
            for (int pp = 0; pp < PP; pp++) {
                uint32_t bd = base + (BOF + (s * 16 + arow) * BROW + wn + pp * 16 + ahalf * 8) * 2;
                uint32_t r0, r1, r2, r3;
                LDSM4T(r0, r1, r2, r3, bd);
                bh[b][2 * pp][0] = r0; bh[b][2 * pp][1] = r1;
                bh[b][2 * pp + 1][0] = r2; bh[b][2 * pp + 1][1] = r3;
                LDSM4T(r0, r1, r2, r3, bd + BSZH * 2);
                bl[b][2 * pp][0] = r0; bl[b][2 * pp][1] = r1;
                bl[b][2 * pp + 1][0] = r2; bl[b][2 * pp + 1][1] = r3;
            }
        }
    };

    auto mma_all = [&](int b) {
        // term-major: consecutive MMAs hit different accumulators
#pragma unroll
        for (int ns = 0; ns < NS; ns++)
#pragma unroll
            for (int ms = 0; ms < 2; ms++)
                mma_bf16(acc[ms][ns], ah[b][ms], bh[b][ns][0], bh[b][ns][1]);
#pragma unroll
        for (int ns = 0; ns < NS; ns++)
#pragma unroll
            for (int ms = 0; ms < 2; ms++)
                mma_bf16(acc[ms][ns], ah[b][ms], bl[b][ns][0], bl[b][ns][1]);
#pragma unroll
        for (int ns = 0; ns < NS; ns++)
#pragma unroll
            for (int ms = 0; ms < 2; ms++)
                mma_bf16(acc[ms][ns], al[b][ms], bh[b][ns][0], bh[b][ns][1]);
    };

    int T = Kd / 64;
    load_tile(0, 0);
    uint32_t smem_base = (uint32_t)__cvta_generic_to_shared(smg);

    for (int t = 0; t < T; t++) {
        asm volatile("cp.async.wait_group 0;\n");
        __syncthreads();
        if (t + 1 < T) load_tile((t + 1) & 1, (t + 1) * 64);
        base = smem_base + (t & 1) * STG * 2;
        load_frags(0, 0);
#pragma unroll
        for (int s = 0; s < 4; s++) {
            if (s < 3) load_frags((s + 1) & 1, s + 1);
            mma_all(s & 1);
        }
        __syncthreads();
    }

    // epilogue
#pragma unroll
    for (int ms = 0; ms < 2; ms++) {
        int i0 = bm + wm + ms * 16 + r;
#pragma unroll
        for (int ns = 0; ns < NS; ns++) {
            int j = bn + wn + ns * 8 + 2 * cc;
            float v00 = acc[ms][ns][0] * alpha, v01 = acc[ms][ns][1] * alpha;
            float v10 = acc[ms][ns][2] * alpha, v11 = acc[ms][ns][3] * alpha;
            if (bias) {
                float bj0 = bias[j], bj1 = bias[j + 1];
                v00 += bj0; v01 += bj1; v10 += bj0; v11 += bj1;
            }
            if (act == 1) {
                v00 = gelu_exact(v00); v01 = gelu_exact(v01);
                v10 = gelu_exact(v10); v11 = gelu_exact(v11);
            }
            if (add) {
                v00 += add[(size_t)i0 * ldadd + j];
                v01 += add[(size_t)i0 * ldadd + j + 1];
                v10 += add[(size_t)(i0 + 8) * ldadd + j];
                v11 += add[(size_t)(i0 + 8) * ldadd + j + 1];
            }
            if (Cf) {
                float2 a2; a2.x = v00; a2.y = v01;
                float2 b2; b2.x = v10; b2.y = v11;
                *(float2*)(Cf + (size_t)i0 * ldc + j) = a2;
                *(float2*)(Cf + (size_t)(i0 + 8) * ldc + j) = b2;
            }
            if (Ch) {
                bf16 h00, l00, h01, l01, h10, l10, h11, l11;
                split1(v00, h00, l00); split1(v01, h01, l01);
                split1(v10, h10, l10); split1(v11, h11, l11);
                *(bf162*)(Ch + (size_t)i0 * ldch + j) = bf162(h00, h01);
                *(bf162*)(Cl + (size_t)i0 * ldch + j) = bf162(l00, l01);
                *(bf162*)(Ch + (size_t)(i0 + 8) * ldch + j) = bf162(h10, h11);
                *(bf162*)(Cl + (size_t)(i0 + 8) * ldch + j) = bf162(l10, l11);
            }
        }
    }
}

// ---------------- launcher ----------------
#define SYM(p, s) cudaGetSymbolAddress((void**)&p, s)

extern "C" void kernel_launch(void* const* d_in, const int* in_sizes, int n_in,
                              void* d_out, int out_size) {
    const float* vis       = (const float*)d_in[0];
    const float* slot_init = (const float*)d_in[1];
    const float* ln_vis_g  = (const float*)d_in[2];
    const float* ln_vis_b  = (const float*)d_in[3];
    const float* ln_sl_g   = (const float*)d_in[4];
    const float* ln_sl_b   = (const float*)d_in[5];
    const float* Wq        = (const float*)d_in[6];
    const float* Wk        = (const float*)d_in[7];
    const float* Wv        = (const float*)d_in[8];
    const float* Wo        = (const float*)d_in[9];
    const float* mha_in_w  = (const float*)d_in[10];
    const float* mha_in_b  = (const float*)d_in[11];
    const float* mha_out_w = (const float*)d_in[12];
    const float* mha_out_b = (const float*)d_in[13];
    const float* ln_sa_g   = (const float*)d_in[14];
    const float* ln_sa_b   = (const float*)d_in[15];
    const float* ln_ffn_g  = (const float*)d_in[16];
    const float* ln_ffn_b  = (const float*)d_in[17];
    const float* W1        = (const float*)d_in[18];
    const float* b1        = (const float*)d_in[19];
    const float* W2        = (const float*)d_in[20];
    const float* b2        = (const float*)d_in[21];

    bf16 *vnh, *vnl, *Wkh, *Wkl, *Wqh, *Wql, *Wvh, *Wvl, *Woh, *Wol;
    bf16 *Wqkh, *Wqkl, *Wvoh, *Wvol, *miwh, *miwl, *mowh, *mowl;
    bf16 *W1h, *W1l, *W2h, *W2l, *snh, *snl, *qh, *ql, *awh, *awl;
    bf16 *u1h, *u1l, *slbh, *slbl, *sah, *sal, *hh, *hl, *tbh, *tbl;
    float *slots, *attn, *qkv, *P, *tmp;
    SYM(vnh, g_vnh); SYM(vnl, g_vnl);
    SYM(Wkh, g_Wkh); SYM(Wkl, g_Wkl); SYM(Wqh, g_Wqh); SYM(Wql, g_Wql);
    SYM(Wvh, g_Wvh); SYM(Wvl, g_Wvl); SYM(Woh, g_Woh); SYM(Wol, g_Wol);
    SYM(Wqkh, g_Wqkh); SYM(Wqkl, g_Wqkl); SYM(Wvoh, g_Wvoh); SYM(Wvol, g_Wvol);
    SYM(miwh, g_miwh); SYM(miwl, g_miwl); SYM(mowh, g_mowh); SYM(mowl, g_mowl);
    SYM(W1h, g_W1h); SYM(W1l, g_W1l); SYM(W2h, g_W2h); SYM(W2l, g_W2l);
    SYM(snh, g_snh); SYM(snl, g_snl); SYM(qh, g_qh); SYM(ql, g_ql);
    SYM(awh, g_awh); SYM(awl, g_awl); SYM(u1h, g_u1h); SYM(u1l, g_u1l);
    SYM(slbh, g_slbh); SYM(slbl, g_slbl); SYM(sah, g_sah); SYM(sal, g_sal);
    SYM(hh, g_hh); SYM(hl, g_hl); SYM(tbh, g_tbh); SYM(tbl, g_tbl);
    SYM(slots, g_slots); SYM(attn, g_attn); SYM(qkv, g_qkv); SYM(P, g_P); SYM(tmp, g_tmp);

    float* out = (float*)d_out;

    // smem bytes: STG (bf16) * 2 stages * 2 bytes
    const int SM_128_64  = (2 * 128 * 72 + 2 * 64 * 72) * 2 * 2;    // 110592 (NT and NN identical)
    const int SM_64_128T = (2 * 64 * 72 + 2 * 128 * 72) * 2 * 2;    // 110592
    const int SM_64_64N  = (2 * 64 * 72 + 2 * 64 * 72) * 2 * 2;     // 73728
    cudaFuncSetAttribute(gemmx<true, 128, 64>,  cudaFuncAttributeMaxDynamicSharedMemorySize, SM_128_64);
    cudaFuncSetAttribute(gemmx<false, 128, 64>, cudaFuncAttributeMaxDynamicSharedMemorySize, SM_128_64);
    cudaFuncSetAttribute(gemmx<true, 64, 128>,  cudaFuncAttributeMaxDynamicSharedMemorySize, SM_64_128T);
    cudaFuncSetAttribute(gemmx<false, 64, 64>,  cudaFuncAttributeMaxDynamicSharedMemorySize, SM_64_64N);

    // ---- merged weight split ----
    {
        SJ j;
        j.s[0] = Wq;  j.h[0] = Wqh;  j.l[0] = Wql;
        j.s[1] = Wk;  j.h[1] = Wkh;  j.l[1] = Wkl;
        j.s[2] = Wv;  j.h[2] = Wvh;  j.l[2] = Wvl;
        j.s[3] = Wo;  j.h[3] = Woh;  j.l[3] = Wol;
        j.s[4] = mha_out_w; j.h[4] = mowh; j.l[4] = mowl;
        j.s[5] = mha_in_w;  j.h[5] = miwh; j.l[5] = miwl;
        j.s[6] = W1;  j.h[6] = W1h;  j.l[6] = W1l;
        j.s[7] = W2;  j.h[7] = W2h;  j.l[7] = W2l;
        int blocks[8] = {1024, 1024, 1024, 1024, 1024, 3072, 2048, 2048};
        j.cum[0] = 0;
        for (int i = 0; i < 8; i++) j.cum[i + 1] = j.cum[i] + blocks[i];
        split_all<<<j.cum[8], 256>>>(j);
    }

    // vn = LN(visual_tokens) -> split bf16
    ln_kernel<<<Bb * Nn, 256>>>(vis, nullptr, ln_vis_g, ln_vis_b, nullptr, vnh, vnl);

    // Wqk = Wq @ Wk^T (NT); Wvo = Wv @ Wo (NN)
    gemmx<true, 128, 64><<<dim3(16, 8, 1), 256, SM_128_64>>>(Wqh, Wql, Wkh, Wkl, Dd, Dd, 0, 0, 1.0f,
        nullptr, 0, 0, Wqkh, Wqkl, Dd, 0, nullptr, nullptr, 0, 0, 0);
    gemmx<false, 128, 64><<<dim3(16, 8, 1), 256, SM_128_64>>>(Wvh, Wvl, Woh, Wol, Dd, Dd, 0, 0, 1.0f,
        nullptr, 0, 0, Wvoh, Wvol, Dd, 0, nullptr, nullptr, 0, 0, 0);

    bcast_slots<<<(Bb * KS * Dd) / 256, 256>>>(slot_init, slots);

    const int Mfull = Bb * KS;  // 1024
    for (int it = 0; it < 2; it++) {
        ln_kernel<<<Mfull, 256>>>(slots, nullptr, ln_sl_g, ln_sl_b, nullptr, snh, snl);
        // q = sn @ Wqk  (NN)
        gemmx<false, 128, 64><<<dim3(16, 8, 1), 256, SM_128_64>>>(snh, snl, Wqkh, Wqkl, Dd, Dd, 0, 0, 1.0f,
            nullptr, 0, 0, qh, ql, Dd, 0, nullptr, nullptr, 0, 0, 0);
        // attn[b] = (1/32) q[b] @ vn[b]^T  (NT, M=64, N=4096)
        gemmx<true, 64, 128><<<dim3(32, 1, Bb), 128, SM_64_128T>>>(qh, ql, vnh, vnl, Dd, Dd,
            (long long)KS * Dd, (long long)Nn * Dd, 0.03125f,
            attn, Nn, (long long)KS * Nn, nullptr, nullptr, 0, 0,
            nullptr, nullptr, 0, 0, 0);
        softmax_slots<<<(Bb * Nn) / 256, 256>>>(attn, awh, awl);
        // u1[b] = aw[b] @ vn[b]  (NN, M=64, K=4096)
        gemmx<false, 64, 64><<<dim3(16, 1, Bb), 128, SM_64_64N>>>(awh, awl, vnh, vnl, Nn, Dd,
            (long long)KS * Nn, (long long)Nn * Dd, 1.0f,
            nullptr, 0, 0, u1h, u1l, Dd, (long long)KS * Dd,
            nullptr, nullptr, 0, 0, 0);
        // slots = slots + u1 @ Wvo  (NN)
        gemmx<false, 128, 64><<<dim3(16, 8, 1), 256, SM_128_64>>>(u1h, u1l, Wvoh, Wvol, Dd, Dd, 0, 0, 1.0f,
            slots, Dd, 0, slbh, slbl, Dd, 0, nullptr, slots, Dd, 0, 0);
        // qkv = slots @ mha_in_w^T + b  (NT, N=3072)
        gemmx<true, 128, 64><<<dim3(48, 8, 1), 256, SM_128_64>>>(slbh, slbl, miwh, miwl, Dd, Dd, 0, 0, 1.0f,
            qkv, 3 * Dd, 0, nullptr, nullptr, 0, 0, mha_in_b, nullptr, 0, 0, 0);
        mha_scores<<<Bb * Hh, 256>>>(qkv, P);
        mha_av<<<Bb * Hh, 256>>>(qkv, P, sah, sal);
        // tmp = sa @ mha_out_w^T + b  (NT)
        gemmx<true, 128, 64><<<dim3(16, 8, 1), 256, SM_128_64>>>(sah, sal, mowh, mowl, Dd, Dd, 0, 0, 1.0f,
            tmp, Dd, 0, nullptr, nullptr, 0, 0, mha_out_b, nullptr, 0, 0, 0);
        ln_kernel<<<Mfull, 256>>>(slots, tmp, ln_sa_g, ln_sa_b, slots, nullptr, nullptr);
    }

    ln_kernel<<<Mfull, 256>>>(slots, nullptr, ln_ffn_g, ln_ffn_b, nullptr, hh, hl);
    // tb = gelu(h @ W1 + b1)  (NN, N=2048)
    gemmx<false, 128, 64><<<dim3(32, 8, 1), 256, SM_128_64>>>(hh, hl, W1h, W1l, Dd, 2 * Dd, 0, 0, 1.0f,
        nullptr, 0, 0, tbh, tbl, 2 * Dd, 0, b1, nullptr, 0, 0, 1);
    // out = slots + tb @ W2 + b2  (NN, K=2048)
    gemmx<false, 128, 64><<<dim3(16, 8, 1), 256, SM_128_64>>>(tbh, tbl, W2h, W2l, 2 * Dd, Dd, 0, 0, 1.0f,
        out, Dd, 0, nullptr, nullptr, 0, 0, b2, slots, Dd, 0, 0);
}